// round 10
// baseline (speedup 1.0000x reference)
#include <cuda_runtime.h>
#include <cuda_fp16.h>
#include <math.h>
#include <stdint.h>

// ---------------------------------------------------------------------------
// Problem constants
// ---------------------------------------------------------------------------
#define S_LEN 1024
#define BATCH 4
#define EMB   1024
#define NH    16
#define HD    64
#define NTOK  (S_LEN * BATCH)     // 4096 tokens, token index t = s*BATCH + b
#define LN_EPS 1e-5f

// ---------------------------------------------------------------------------
// Scratch (device globals -- allocation-free kernel_launch requirement)
// ---------------------------------------------------------------------------
__device__ __half g_h  [NTOK * EMB];          // ln output (half)
__device__ float  g_qkv[NTOK * 3 * EMB];      // qkv (fp32, attention reads it)
__device__ __half g_a  [NTOK * EMB];          // attn out (half)
__device__ float  g_x2 [NTOK * EMB];          // x + attn residual (fp32)
__device__ __half g_m  [NTOK * 4 * EMB];      // gelu out (half)
__device__ __half g_wt [12 * EMB * EMB];      // transposed half weights [N][K]
__device__ float  g_vt [NH * BATCH * HD * S_LEN];  // V transposed (tf32 vals)

// ---------------------------------------------------------------------------
// TF32 helpers (attention path)
// ---------------------------------------------------------------------------
__device__ __forceinline__ uint32_t f2tf32(float x) {
    uint32_t u;
    asm("cvt.rna.tf32.f32 %0, %1;" : "=r"(u) : "f"(x));
    return u;
}
__device__ __forceinline__ float tf32r(float x) {
    return __uint_as_float(f2tf32(x));
}
__device__ __forceinline__ void mma_tf32(
    float c[4], const uint32_t a[4], const uint32_t b[2])
{
    asm volatile(
        "mma.sync.aligned.m16n8k8.row.col.f32.tf32.tf32.f32 "
        "{%0,%1,%2,%3}, {%4,%5,%6,%7}, {%8,%9}, {%0,%1,%2,%3};\n"
        : "+f"(c[0]), "+f"(c[1]), "+f"(c[2]), "+f"(c[3])
        : "r"(a[0]), "r"(a[1]), "r"(a[2]), "r"(a[3]),
          "r"(b[0]), "r"(b[1]));
}

// fp16 mma: m16n8k16, fp32 accumulate
__device__ __forceinline__ void mma_f16(
    float c[4], const uint32_t a[4], const uint32_t b[2])
{
    asm volatile(
        "mma.sync.aligned.m16n8k16.row.col.f32.f16.f16.f32 "
        "{%0,%1,%2,%3}, {%4,%5,%6,%7}, {%8,%9}, {%0,%1,%2,%3};\n"
        : "+f"(c[0]), "+f"(c[1]), "+f"(c[2]), "+f"(c[3])
        : "r"(a[0]), "r"(a[1]), "r"(a[2]), "r"(a[3]),
          "r"(b[0]), "r"(b[1]));
}

// cp.async helpers
__device__ __forceinline__ void cp_async16(void* smem_ptr, const void* gptr) {
    uint32_t s = (uint32_t)__cvta_generic_to_shared(smem_ptr);
    asm volatile("cp.async.cg.shared.global [%0], [%1], 16;\n"
                 :: "r"(s), "l"(gptr));
}
__device__ __forceinline__ void cp_commit() {
    asm volatile("cp.async.commit_group;\n");
}
template <int N>
__device__ __forceinline__ void cp_wait() {
    asm volatile("cp.async.wait_group %0;\n" :: "n"(N));
}

// ---------------------------------------------------------------------------
// Weight transpose+convert: src [K][N] fp32 -> dst [N][K] half
// grid (N/32, K/32), block (32, 8)
// ---------------------------------------------------------------------------
__global__ void __launch_bounds__(256) wtrans_kernel(
    const float* __restrict__ src, __half* __restrict__ dst, int K, int N)
{
    __shared__ float tile[32][33];
    const int n0 = blockIdx.x * 32, k0 = blockIdx.y * 32;
    const int tx = threadIdx.x, ty = threadIdx.y;

    #pragma unroll
    for (int i = 0; i < 4; i++) {
        int k = k0 + ty * 4 + i;
        tile[ty * 4 + i][tx] = src[(size_t)k * N + n0 + tx];
    }
    __syncthreads();
    #pragma unroll
    for (int i = 0; i < 4; i++) {
        int n = n0 + ty * 4 + i;
        dst[(size_t)n * K + k0 + tx] = __float2half_rn(tile[tx][ty * 4 + i]);
    }
}

// ---------------------------------------------------------------------------
// LayerNorm (writes half: only ever feeds GEMM A-operands)
// ---------------------------------------------------------------------------
__global__ void __launch_bounds__(256) ln_kernel(
    const float* __restrict__ x, const float* __restrict__ gamma,
    const float* __restrict__ beta, __half* __restrict__ out)
{
    const int row = blockIdx.x;
    const int t   = threadIdx.x;
    const float4* xr = reinterpret_cast<const float4*>(x + (size_t)row * EMB);
    float4 v = xr[t];

    float s  = v.x + v.y + v.z + v.w;
    float sq = v.x * v.x + v.y * v.y + v.z * v.z + v.w * v.w;
    #pragma unroll
    for (int m = 16; m > 0; m >>= 1) {
        s  += __shfl_xor_sync(0xffffffffu, s,  m);
        sq += __shfl_xor_sync(0xffffffffu, sq, m);
    }

    __shared__ float sh_s[8], sh_q[8];
    __shared__ float sh_mean, sh_rstd;
    const int warp = t >> 5, lane = t & 31;
    if (lane == 0) { sh_s[warp] = s; sh_q[warp] = sq; }
    __syncthreads();
    if (t == 0) {
        float ts = 0.f, tq = 0.f;
        #pragma unroll
        for (int i = 0; i < 8; i++) { ts += sh_s[i]; tq += sh_q[i]; }
        float mean = ts * (1.0f / EMB);
        float var  = tq * (1.0f / EMB) - mean * mean;
        sh_mean = mean;
        sh_rstd = rsqrtf(var + LN_EPS);
    }
    __syncthreads();
    const float mean = sh_mean, rstd = sh_rstd;

    float4 g4 = reinterpret_cast<const float4*>(gamma)[t];
    float4 b4 = reinterpret_cast<const float4*>(beta)[t];
    __half2 h01 = __floats2half2_rn((v.x - mean) * rstd * g4.x + b4.x,
                                    (v.y - mean) * rstd * g4.y + b4.y);
    __half2 h23 = __floats2half2_rn((v.z - mean) * rstd * g4.z + b4.z,
                                    (v.w - mean) * rstd * g4.w + b4.w);
    __half2* o = reinterpret_cast<__half2*>(out + (size_t)row * EMB + t * 4);
    o[0] = h01; o[1] = h23;
}

// ---------------------------------------------------------------------------
// GELU (GPT-2 tanh approximation)
// ---------------------------------------------------------------------------
__device__ __forceinline__ float gelu_f(float x) {
    const float c = 0.7978845608028654f;   // sqrt(2/pi)
    float x3 = x * x * x;
    return 0.5f * x * (1.0f + tanhf(c * (x + 0.044715f * x3)));
}

// ---------------------------------------------------------------------------
// FP16 tensor-core GEMM, cp.async 3-stage pipeline.
//   C[M,N] = A[M,K] @ Wt[N,K]^T + bias; EPI 0:none 1:+res 2:gelu->half
// A half [M][K] row-major; Wt half [N][K] row-major (pre-transposed).
// 128x128x32 block tile, 8 warps (2x4), 64x32 warp tile, m16n8k16.
// Smem per stage: As [128][40] half, Bs [128][40] half (row stride 20 u32 --
// fragment lanes hit banks {20g+q mod 32} = all-distinct, conflict-free).
// ---------------------------------------------------------------------------
#define HST 20                            // row stride in u32 (40 halves)
#define H_STG_HALF (128 * 40)             // halves per operand per stage
#define H_STG_U32  (128 * HST)            // 2560 u32
#define HG_STG (2 * H_STG_U32)            // 5120 u32 = 20480 B per stage
#define HNSTAGE 3
#define GEMM_SMEM_BYTES (HNSTAGE * HG_STG * 4)   // 61440 B

template <int EPI>
__global__ void __launch_bounds__(256, 2) gemm_f16(
    int M, int N, int K,
    const __half* __restrict__ A, const __half* __restrict__ Wt,
    const float* __restrict__ bias, const float* __restrict__ res,
    void* __restrict__ Cv)
{
    extern __shared__ uint32_t smem_u[];

    const int bm = blockIdx.y, bn = blockIdx.x;
    const int t    = threadIdx.x;
    const int warp = t >> 5, lane = t & 31;
    const int wm = warp >> 2;               // 0..1 : 64-row slab
    const int wn = warp & 3;                // 0..3 : 32-col slab
    const int g  = lane >> 2;               // 0..7
    const int q  = lane & 3;                // 0..3

    // staging: 128 rows x 32 halves per operand = 512 x 16B chunks; 2/thread
    const int srow = t >> 2;                // 0..63, +64 for i=1
    const int scs  = t & 3;                 // 16B chunk within row
    const __half* aSrc = A  + (size_t)(bm * 128 + srow) * K + scs * 8;
    const __half* bSrc = Wt + (size_t)(bn * 128 + srow) * K + scs * 8;
    const int sDst = srow * HST + scs * 4;  // u32 offset

    float acc[4][4][4];
    #pragma unroll
    for (int mi = 0; mi < 4; mi++)
        #pragma unroll
        for (int ni = 0; ni < 4; ni++)
            #pragma unroll
            for (int j = 0; j < 4; j++) acc[mi][ni][j] = 0.f;

    #define ISSUE(stg, kt)                                                     \
        {                                                                      \
            uint32_t* as = smem_u + (stg) * HG_STG;                            \
            uint32_t* bs = as + H_STG_U32;                                     \
            _Pragma("unroll")                                                  \
            for (int i = 0; i < 2; i++) {                                      \
                cp_async16(as + sDst + i * (64 * HST),                         \
                           aSrc + (size_t)(kt) * 32 + (size_t)i * 64 * K);     \
                cp_async16(bs + sDst + i * (64 * HST),                         \
                           bSrc + (size_t)(kt) * 32 + (size_t)i * 64 * K);     \
            }                                                                  \
        }

    const int ntiles = K / 32;
    ISSUE(0, 0); cp_commit();
    ISSUE(1, 1); cp_commit();

    int buf = 0;
    for (int kt = 0; kt < ntiles; kt++) {
        cp_wait<1>();
        __syncthreads();

        if (kt + 2 < ntiles) {
            int nstg = buf + 2; if (nstg >= HNSTAGE) nstg -= HNSTAGE;
            ISSUE(nstg, kt + 2);
        }
        cp_commit();

        // ---- compute on stage `buf` ----
        {
            const uint32_t* as = smem_u + buf * HG_STG + (wm * 64 + g) * HST;
            const uint32_t* bs = smem_u + buf * HG_STG + H_STG_U32
                                 + (wn * 32 + g) * HST;
            #pragma unroll
            for (int ks = 0; ks < 2; ks++) {
                const int ko = ks * 8 + q;     // u32 col within row
                uint32_t af[4][4], bf[4][2];
                #pragma unroll
                for (int mi = 0; mi < 4; mi++) {
                    const uint32_t* p = as + mi * 16 * HST + ko;
                    af[mi][0] = p[0];
                    af[mi][1] = p[8 * HST];
                    af[mi][2] = p[4];
                    af[mi][3] = p[8 * HST + 4];
                }
                #pragma unroll
                for (int ni = 0; ni < 4; ni++) {
                    const uint32_t* p = bs + ni * 8 * HST + ko;
                    bf[ni][0] = p[0];
                    bf[ni][1] = p[4];
                }
                #pragma unroll
                for (int mi = 0; mi < 4; mi++)
                    #pragma unroll
                    for (int ni = 0; ni < 4; ni++)
                        mma_f16(acc[mi][ni], af[mi], bf[ni]);
            }
        }

        buf++; if (buf == HNSTAGE) buf = 0;
    }
    #undef ISSUE

    // ---- epilogue ----
    float*  Cf = reinterpret_cast<float*>(Cv);
    __half* Ch = reinterpret_cast<__half*>(Cv);
    const int row_base = bm * 128 + wm * 64;
    const int col_base = bn * 128 + wn * 32;
    #pragma unroll
    for (int mi = 0; mi < 4; mi++) {
        #pragma unroll
        for (int ni = 0; ni < 4; ni++) {
            const int col = col_base + ni * 8 + 2 * q;
            const float b0 = bias[col], b1 = bias[col + 1];
            #pragma unroll
            for (int half_i = 0; half_i < 2; half_i++) {
                const int row = row_base + mi * 16 + g + half_i * 8;
                const size_t base = (size_t)row * N + col;
                float v0 = acc[mi][ni][half_i * 2 + 0] + b0;
                float v1 = acc[mi][ni][half_i * 2 + 1] + b1;
                if (EPI == 1) { v0 += res[base]; v1 += res[base + 1]; }
                if (EPI == 2) {
                    *reinterpret_cast<__half2*>(Ch + base) =
                        __floats2half2_rn(gelu_f(v0), gelu_f(v1));
                } else {
                    *reinterpret_cast<float2*>(Cf + base) = make_float2(v0, v1);
                }
            }
        }
    }
}

// ---------------------------------------------------------------------------
// V transpose: qkv V slice -> vt[bh][d][s], tf32-rounded.
// ---------------------------------------------------------------------------
__global__ void __launch_bounds__(256) vtrans_kernel(
    const float* __restrict__ qkv, float* __restrict__ vt)
{
    __shared__ float tile[32][33];
    const int bh = blockIdx.x, b = bh >> 4, h = bh & 15;
    const int s0 = blockIdx.y * 32, d0 = blockIdx.z * 32;
    const int tx = threadIdx.x, ty = threadIdx.y;

    #pragma unroll
    for (int i = 0; i < 4; i++) {
        int s = s0 + ty * 4 + i;
        tile[ty * 4 + i][tx] =
            qkv[((size_t)s * BATCH + b) * (3 * EMB) + 2 * EMB + h * HD + d0 + tx];
    }
    __syncthreads();
    #pragma unroll
    for (int i = 0; i < 4; i++) {
        int d = d0 + ty * 4 + i;
        vt[((size_t)bh * HD + d) * S_LEN + s0 + tx] = tf32r(tile[tx][ty * 4 + i]);
    }
}

// ---------------------------------------------------------------------------
// Flash attention on tensor cores (tf32 m16n8k8), online softmax. (proven)
// Output written as HALF (feeds proj GEMM A operand).
// ---------------------------------------------------------------------------
#define ATS 68
#define ATTN_SMEM_BYTES (3 * 64 * ATS * 4)   // 52224

__global__ void __launch_bounds__(128) attn_mma_kernel(
    const float* __restrict__ qkv, const float* __restrict__ vt,
    __half* __restrict__ out)
{
    extern __shared__ float sm[];
    float* Ks  = sm;
    float* Vts = sm + 64 * ATS;
    float* Ps  = sm + 2 * 64 * ATS;

    const int bh = blockIdx.x, b = bh >> 4, h = bh & 15;
    const int q0 = blockIdx.y * 64;
    const int t = threadIdx.x, w = t >> 5, lane = t & 31;
    const int g = lane >> 2, q = lane & 3;
    const int wrow = w * 16;

    #pragma unroll
    for (int i = 0; i < 8; i++) {
        int idx = t + i * 128;
        int r = idx >> 4, c = (idx & 15) << 2;
        float4 v = *reinterpret_cast<const float4*>(
            qkv + ((size_t)(q0 + r) * BATCH + b) * (3 * EMB) + h * HD + c);
        v.x = tf32r(v.x); v.y = tf32r(v.y); v.z = tf32r(v.z); v.w = tf32r(v.w);
        *reinterpret_cast<float4*>(&Ks[r * ATS + c]) = v;
    }
    __syncthreads();

    uint32_t qf[8][4];
    #pragma unroll
    for (int kt = 0; kt < 8; kt++) {
        qf[kt][0] = __float_as_uint(Ks[(wrow + g)     * ATS + kt * 8 + q]);
        qf[kt][1] = __float_as_uint(Ks[(wrow + g + 8) * ATS + kt * 8 + q]);
        qf[kt][2] = __float_as_uint(Ks[(wrow + g)     * ATS + kt * 8 + q + 4]);
        qf[kt][3] = __float_as_uint(Ks[(wrow + g + 8) * ATS + kt * 8 + q + 4]);
    }
    __syncthreads();

    float o[8][4];
    #pragma unroll
    for (int nt = 0; nt < 8; nt++)
        #pragma unroll
        for (int j = 0; j < 4; j++) o[nt][j] = 0.f;
    float m0 = -1e30f, m1 = -1e30f, l0 = 0.f, l1 = 0.f;

    for (int kv0 = 0; kv0 < S_LEN; kv0 += 64) {
        #pragma unroll
        for (int i = 0; i < 8; i++) {
            int idx = t + i * 128;
            int r = idx >> 4, c = (idx & 15) << 2;
            float4 kv4 = *reinterpret_cast<const float4*>(
                qkv + ((size_t)(kv0 + r) * BATCH + b) * (3 * EMB) + EMB + h * HD + c);
            kv4.x = tf32r(kv4.x); kv4.y = tf32r(kv4.y);
            kv4.z = tf32r(kv4.z); kv4.w = tf32r(kv4.w);
            *reinterpret_cast<float4*>(&Ks[r * ATS + c]) = kv4;
            float4 vv4 = *reinterpret_cast<const float4*>(
                vt + ((size_t)bh * HD + r) * S_LEN + kv0 + c);
            *reinterpret_cast<float4*>(&Vts[r * ATS + c]) = vv4;
        }
        __syncthreads();

        float sc[8][4];
        #pragma unroll
        for (int nt = 0; nt < 8; nt++) {
            sc[nt][0] = sc[nt][1] = sc[nt][2] = sc[nt][3] = 0.f;
            #pragma unroll
            for (int kt = 0; kt < 8; kt++) {
                uint32_t bfr[2];
                bfr[0] = __float_as_uint(Ks[(nt * 8 + g) * ATS + kt * 8 + q]);
                bfr[1] = __float_as_uint(Ks[(nt * 8 + g) * ATS + kt * 8 + q + 4]);
                mma_tf32(sc[nt], qf[kt], bfr);
            }
        }

        float mx0 = -1e30f, mx1 = -1e30f;
        #pragma unroll
        for (int nt = 0; nt < 8; nt++) {
            sc[nt][0] *= 0.125f; sc[nt][1] *= 0.125f;
            sc[nt][2] *= 0.125f; sc[nt][3] *= 0.125f;
            mx0 = fmaxf(mx0, fmaxf(sc[nt][0], sc[nt][1]));
            mx1 = fmaxf(mx1, fmaxf(sc[nt][2], sc[nt][3]));
        }
        mx0 = fmaxf(mx0, __shfl_xor_sync(0xffffffffu, mx0, 1));
        mx0 = fmaxf(mx0, __shfl_xor_sync(0xffffffffu, mx0, 2));
        mx1 = fmaxf(mx1, __shfl_xor_sync(0xffffffffu, mx1, 1));
        mx1 = fmaxf(mx1, __shfl_xor_sync(0xffffffffu, mx1, 2));

        const float mn0 = fmaxf(m0, mx0), mn1 = fmaxf(m1, mx1);
        const float a0 = __expf(m0 - mn0), a1 = __expf(m1 - mn1);
        float s0 = 0.f, s1 = 0.f;
        #pragma unroll
        for (int nt = 0; nt < 8; nt++) {
            float p0 = __expf(sc[nt][0] - mn0);
            float p1 = __expf(sc[nt][1] - mn0);
            float p2 = __expf(sc[nt][2] - mn1);
            float p3 = __expf(sc[nt][3] - mn1);
            s0 += p0 + p1; s1 += p2 + p3;
            *reinterpret_cast<float2*>(&Ps[(wrow + g) * ATS + nt * 8 + 2 * q]) =
                make_float2(tf32r(p0), tf32r(p1));
            *reinterpret_cast<float2*>(&Ps[(wrow + g + 8) * ATS + nt * 8 + 2 * q]) =
                make_float2(tf32r(p2), tf32r(p3));
        }
        s0 += __shfl_xor_sync(0xffffffffu, s0, 1);
        s0 += __shfl_xor_sync(0xffffffffu, s0, 2);
        s1 += __shfl_xor_sync(0xffffffffu, s1, 1);
        s1 += __shfl_xor_sync(0xffffffffu, s1, 2);

        l0 = l0 * a0 + s0; l1 = l1 * a1 + s1;
        m0 = mn0; m1 = mn1;
        #pragma unroll
        for (int nt = 0; nt < 8; nt++) {
            o[nt][0] *= a0; o[nt][1] *= a0;
            o[nt][2] *= a1; o[nt][3] *= a1;
        }
        __syncwarp();

        #pragma unroll
        for (int kt = 0; kt < 8; kt++) {
            uint32_t af[4];
            af[0] = __float_as_uint(Ps[(wrow + g)     * ATS + kt * 8 + q]);
            af[1] = __float_as_uint(Ps[(wrow + g + 8) * ATS + kt * 8 + q]);
            af[2] = __float_as_uint(Ps[(wrow + g)     * ATS + kt * 8 + q + 4]);
            af[3] = __float_as_uint(Ps[(wrow + g + 8) * ATS + kt * 8 + q + 4]);
            #pragma unroll
            for (int nt = 0; nt < 8; nt++) {
                uint32_t bfr[2];
                bfr[0] = __float_as_uint(Vts[(nt * 8 + g) * ATS + kt * 8 + q]);
                bfr[1] = __float_as_uint(Vts[(nt * 8 + g) * ATS + kt * 8 + q + 4]);
                mma_tf32(o[nt], af, bfr);
            }
        }
        __syncthreads();
    }

    const float inv0 = 1.0f / l0, inv1 = 1.0f / l1;
    const int s_row0 = q0 + wrow + g;
    #pragma unroll
    for (int nt = 0; nt < 8; nt++) {
        const int col = h * HD + nt * 8 + 2 * q;
        *reinterpret_cast<__half2*>(
            out + ((size_t)s_row0 * BATCH + b) * EMB + col) =
            __floats2half2_rn(o[nt][0] * inv0, o[nt][1] * inv0);
        *reinterpret_cast<__half2*>(
            out + ((size_t)(s_row0 + 8) * BATCH + b) * EMB + col) =
            __floats2half2_rn(o[nt][2] * inv1, o[nt][3] * inv1);
    }
}

// ---------------------------------------------------------------------------
// Launch
// ---------------------------------------------------------------------------
extern "C" void kernel_launch(void* const* d_in, const int* in_sizes, int n_in,
                              void* d_out, int out_size)
{
    const float* x      = (const float*)d_in[0];
    const float* ln1_g  = (const float*)d_in[1];
    const float* ln1_b  = (const float*)d_in[2];
    const float* w_attn = (const float*)d_in[3];
    const float* b_attn = (const float*)d_in[4];
    const float* w_proj = (const float*)d_in[5];
    const float* b_proj = (const float*)d_in[6];
    const float* ln2_g  = (const float*)d_in[7];
    const float* ln2_b  = (const float*)d_in[8];
    const float* w_fc   = (const float*)d_in[9];
    const float* b_fc   = (const float*)d_in[10];
    const float* w_out  = (const float*)d_in[11];
    const float* b_out  = (const float*)d_in[12];
    float* out = (float*)d_out;

    void *p_h, *p_qkv, *p_a, *p_x2, *p_m, *p_wt, *p_vt;
    cudaGetSymbolAddress(&p_h,   g_h);
    cudaGetSymbolAddress(&p_qkv, g_qkv);
    cudaGetSymbolAddress(&p_a,   g_a);
    cudaGetSymbolAddress(&p_x2,  g_x2);
    cudaGetSymbolAddress(&p_m,   g_m);
    cudaGetSymbolAddress(&p_wt,  g_wt);
    cudaGetSymbolAddress(&p_vt,  g_vt);
    __half* h   = (__half*)p_h;
    float*  qkv = (float*)p_qkv;
    __half* a   = (__half*)p_a;
    float*  x2  = (float*)p_x2;
    __half* mm  = (__half*)p_m;
    __half* wt  = (__half*)p_wt;
    float*  vt  = (float*)p_vt;

    __half* wt_attn = wt;                       // [3E][E]
    __half* wt_proj = wt + 3 * EMB * EMB;       // [E][E]
    __half* wt_fc   = wt + 4 * EMB * EMB;       // [4E][E]
    __half* wt_out  = wt + 8 * EMB * EMB;       // [E][4E]

    cudaFuncSetAttribute(attn_mma_kernel,
                         cudaFuncAttributeMaxDynamicSharedMemorySize,
                         ATTN_SMEM_BYTES);
    cudaFuncSetAttribute(gemm_f16<0>,
                         cudaFuncAttributeMaxDynamicSharedMemorySize,
                         GEMM_SMEM_BYTES);
    cudaFuncSetAttribute(gemm_f16<1>,
                         cudaFuncAttributeMaxDynamicSharedMemorySize,
                         GEMM_SMEM_BYTES);
    cudaFuncSetAttribute(gemm_f16<2>,
                         cudaFuncAttributeMaxDynamicSharedMemorySize,
                         GEMM_SMEM_BYTES);

    // 0. transpose+convert weights to half [N][K]
    wtrans_kernel<<<dim3(3 * EMB / 32, EMB / 32), dim3(32, 8)>>>(
        w_attn, wt_attn, EMB, 3 * EMB);
    wtrans_kernel<<<dim3(EMB / 32, EMB / 32), dim3(32, 8)>>>(
        w_proj, wt_proj, EMB, EMB);
    wtrans_kernel<<<dim3(4 * EMB / 32, EMB / 32), dim3(32, 8)>>>(
        w_fc, wt_fc, EMB, 4 * EMB);
    wtrans_kernel<<<dim3(EMB / 32, 4 * EMB / 32), dim3(32, 8)>>>(
        w_out, wt_out, 4 * EMB, EMB);

    // 1. ln1 (half output)
    ln_kernel<<<NTOK, 256>>>(x, ln1_g, ln1_b, h);
    // 2. qkv = h @ w_attn + b_attn            [4096, 3072] fp32 out
    gemm_f16<0><<<dim3(3 * EMB / 128, NTOK / 128), 256, GEMM_SMEM_BYTES>>>(
        NTOK, 3 * EMB, EMB, h, wt_attn, b_attn, nullptr, qkv);
    // 3a. V transpose for tensor-core PV
    vtrans_kernel<<<dim3(NH * BATCH, S_LEN / 32, HD / 32), dim3(32, 8)>>>(qkv, vt);
    // 3b. attention -> a (half, merged heads, token layout)
    attn_mma_kernel<<<dim3(BATCH * NH, S_LEN / 64), 128, ATTN_SMEM_BYTES>>>(
        qkv, vt, a);
    // 4. x2 = x + a @ w_proj + b_proj         fp32 out
    gemm_f16<1><<<dim3(EMB / 128, NTOK / 128), 256, GEMM_SMEM_BYTES>>>(
        NTOK, EMB, EMB, a, wt_proj, b_proj, x, x2);
    // 5. ln2 (half output)
    ln_kernel<<<NTOK, 256>>>(x2, ln2_g, ln2_b, h);
    // 6. m = gelu(h @ w_fc + b_fc)            [4096, 4096] half out
    gemm_f16<2><<<dim3(4 * EMB / 128, NTOK / 128), 256, GEMM_SMEM_BYTES>>>(
        NTOK, 4 * EMB, EMB, h, wt_fc, b_fc, nullptr, mm);
    // 7. out = x2 + m @ w_out + b_out         fp32 out
    gemm_f16<1><<<dim3(EMB / 128, NTOK / 128), 256, GEMM_SMEM_BYTES>>>(
        NTOK, EMB, 4 * EMB, mm, wt_out, b_out, x2, out);
}

// round 13
// speedup vs baseline: 1.7294x; 1.7294x over previous
#include <cuda_runtime.h>
#include <cuda_fp16.h>
#include <math.h>
#include <stdint.h>

// ---------------------------------------------------------------------------
// Problem constants
// ---------------------------------------------------------------------------
#define S_LEN 1024
#define BATCH 4
#define EMB   1024
#define NH    16
#define HD    64
#define NTOK  (S_LEN * BATCH)
#define LN_EPS 1e-5f

// ---------------------------------------------------------------------------
// Scratch (device globals -- allocation-free kernel_launch requirement)
// ---------------------------------------------------------------------------
__device__ __half g_h  [NTOK * EMB];          // ln output (half)
__device__ float  g_qkv[NTOK * 3 * EMB];      // qkv (fp32, attention reads it)
__device__ __half g_a  [NTOK * EMB];          // attn out (half)
__device__ float  g_x2 [NTOK * EMB];          // x + attn residual (fp32)
__device__ __half g_m  [NTOK * 4 * EMB];      // gelu out (half)
__device__ __half g_wt [12 * EMB * EMB];      // transposed half weights [N][K]
__device__ float  g_vt [NH * BATCH * HD * S_LEN];  // V transposed (tf32 vals)

// ---------------------------------------------------------------------------
// helpers
// ---------------------------------------------------------------------------
__device__ __forceinline__ uint32_t f2tf32(float x) {
    uint32_t u;
    asm("cvt.rna.tf32.f32 %0, %1;" : "=r"(u) : "f"(x));
    return u;
}
__device__ __forceinline__ float tf32r(float x) {
    return __uint_as_float(f2tf32(x));
}
__device__ __forceinline__ void mma_tf32(
    float c[4], const uint32_t a[4], const uint32_t b[2])
{
    asm volatile(
        "mma.sync.aligned.m16n8k8.row.col.f32.tf32.tf32.f32 "
        "{%0,%1,%2,%3}, {%4,%5,%6,%7}, {%8,%9}, {%0,%1,%2,%3};\n"
        : "+f"(c[0]), "+f"(c[1]), "+f"(c[2]), "+f"(c[3])
        : "r"(a[0]), "r"(a[1]), "r"(a[2]), "r"(a[3]),
          "r"(b[0]), "r"(b[1]));
}

// fp16 mma: m16n8k16, fp32 accumulate
__device__ __forceinline__ void mma_f16(
    float c[4], const uint32_t a[4], const uint32_t b[2])
{
    asm volatile(
        "mma.sync.aligned.m16n8k16.row.col.f32.f16.f16.f32 "
        "{%0,%1,%2,%3}, {%4,%5,%6,%7}, {%8,%9}, {%0,%1,%2,%3};\n"
        : "+f"(c[0]), "+f"(c[1]), "+f"(c[2]), "+f"(c[3])
        : "r"(a[0]), "r"(a[1]), "r"(a[2]), "r"(a[3]),
          "r"(b[0]), "r"(b[1]));
}

// ldmatrix x4 (b16): 4 8x8 tiles, per-lane row addresses
#define LDSM_X4(r0, r1, r2, r3, addr)                                          \
    asm volatile(                                                              \
        "ldmatrix.sync.aligned.m8n8.x4.shared.b16 {%0,%1,%2,%3}, [%4];"        \
        : "=r"(r0), "=r"(r1), "=r"(r2), "=r"(r3) : "r"(addr))

// cp.async helpers
__device__ __forceinline__ void cp_async16(void* smem_ptr, const void* gptr) {
    uint32_t s = (uint32_t)__cvta_generic_to_shared(smem_ptr);
    asm volatile("cp.async.cg.shared.global [%0], [%1], 16;\n"
                 :: "r"(s), "l"(gptr));
}
__device__ __forceinline__ void cp_commit() {
    asm volatile("cp.async.commit_group;\n");
}
template <int N>
__device__ __forceinline__ void cp_wait() {
    asm volatile("cp.async.wait_group %0;\n" :: "n"(N));
}

// ---------------------------------------------------------------------------
// Weight transpose+convert: src [K][N] fp32 -> dst [N][K] half   (proven)
// ---------------------------------------------------------------------------
__global__ void __launch_bounds__(256) wtrans_kernel(
    const float* __restrict__ src, __half* __restrict__ dst, int K, int N)
{
    __shared__ float tile[32][33];
    const int n0 = blockIdx.x * 32, k0 = blockIdx.y * 32;
    const int tx = threadIdx.x, ty = threadIdx.y;

    #pragma unroll
    for (int i = 0; i < 4; i++) {
        int k = k0 + ty * 4 + i;
        tile[ty * 4 + i][tx] = src[(size_t)k * N + n0 + tx];
    }
    __syncthreads();
    #pragma unroll
    for (int i = 0; i < 4; i++) {
        int n = n0 + ty * 4 + i;
        dst[(size_t)n * K + k0 + tx] = __float2half_rn(tile[tx][ty * 4 + i]);
    }
}

// ---------------------------------------------------------------------------
// LayerNorm (writes half: only ever feeds GEMM A-operands)       (proven)
// ---------------------------------------------------------------------------
__global__ void __launch_bounds__(256) ln_kernel(
    const float* __restrict__ x, const float* __restrict__ gamma,
    const float* __restrict__ beta, __half* __restrict__ out)
{
    const int row = blockIdx.x;
    const int t   = threadIdx.x;
    const float4* xr = reinterpret_cast<const float4*>(x + (size_t)row * EMB);
    float4 v = xr[t];

    float s  = v.x + v.y + v.z + v.w;
    float sq = v.x * v.x + v.y * v.y + v.z * v.z + v.w * v.w;
    #pragma unroll
    for (int m = 16; m > 0; m >>= 1) {
        s  += __shfl_xor_sync(0xffffffffu, s,  m);
        sq += __shfl_xor_sync(0xffffffffu, sq, m);
    }

    __shared__ float sh_s[8], sh_q[8];
    __shared__ float sh_mean, sh_rstd;
    const int warp = t >> 5, lane = t & 31;
    if (lane == 0) { sh_s[warp] = s; sh_q[warp] = sq; }
    __syncthreads();
    if (t == 0) {
        float ts = 0.f, tq = 0.f;
        #pragma unroll
        for (int i = 0; i < 8; i++) { ts += sh_s[i]; tq += sh_q[i]; }
        float mean = ts * (1.0f / EMB);
        float var  = tq * (1.0f / EMB) - mean * mean;
        sh_mean = mean;
        sh_rstd = rsqrtf(var + LN_EPS);
    }
    __syncthreads();
    const float mean = sh_mean, rstd = sh_rstd;

    float4 g4 = reinterpret_cast<const float4*>(gamma)[t];
    float4 b4 = reinterpret_cast<const float4*>(beta)[t];
    __half2 h01 = __floats2half2_rn((v.x - mean) * rstd * g4.x + b4.x,
                                    (v.y - mean) * rstd * g4.y + b4.y);
    __half2 h23 = __floats2half2_rn((v.z - mean) * rstd * g4.z + b4.z,
                                    (v.w - mean) * rstd * g4.w + b4.w);
    __half2* o = reinterpret_cast<__half2*>(out + (size_t)row * EMB + t * 4);
    o[0] = h01; o[1] = h23;
}

// ---------------------------------------------------------------------------
// GELU (GPT-2 tanh approximation)
// ---------------------------------------------------------------------------
__device__ __forceinline__ float gelu_f(float x) {
    const float c = 0.7978845608028654f;
    float x3 = x * x * x;
    return 0.5f * x * (1.0f + tanhf(c * (x + 0.044715f * x3)));
}

// ---------------------------------------------------------------------------
// FP16 tensor-core GEMM, cp.async 3-stage pipeline, LDMATRIX fragment loads.
//   C[M,N] = A[M,K] @ Wt[N,K]^T + bias; EPI 0:none 1:+res 2:gelu->half
// A half [M][K] row-major; Wt half [N][K] row-major (pre-transposed).
// 128x128x32 block tile, 8 warps (2x4), 64x32 warp tile, m16n8k16.
// Smem per stage: As [128][40] half, Bs [128][40] half (row stride 20 u32).
// Fragment loads via ldmatrix.x4: per k32-tile per warp 12 LDSM vs 48 LDS
// (bytes identical, issue slots 4x fewer). 8-row phases read banks
// {20m mod 32} = all-distinct -> conflict-free.
// ---------------------------------------------------------------------------
#define HST 20                            // row stride in u32 (40 halves)
#define H_STG_U32  (128 * HST)            // 2560 u32 per operand per stage
#define HG_STG (2 * H_STG_U32)            // 5120 u32 = 20480 B per stage
#define HNSTAGE 3
#define GEMM_SMEM_BYTES (HNSTAGE * HG_STG * 4)   // 61440 B

template <int EPI>
__global__ void __launch_bounds__(256, 2) gemm_f16(
    int M, int N, int K,
    const __half* __restrict__ A, const __half* __restrict__ Wt,
    const float* __restrict__ bias, const float* __restrict__ res,
    void* __restrict__ Cv)
{
    extern __shared__ uint32_t smem_u[];

    const int bm = blockIdx.y, bn = blockIdx.x;
    const int t    = threadIdx.x;
    const int warp = t >> 5, lane = t & 31;
    const int wm = warp >> 2;               // 0..1 : 64-row slab
    const int wn = warp & 3;                // 0..3 : 32-col slab
    const int g  = lane >> 2;               // 0..7
    const int q  = lane & 3;                // 0..3

    // staging: 128 rows x 32 halves per operand = 512 x 16B chunks; 2/thread
    const int srow = t >> 2;                // 0..63, +64 for i=1
    const int scs  = t & 3;                 // 16B chunk within row
    const __half* aSrc = A  + (size_t)(bm * 128 + srow) * K + scs * 8;
    const __half* bSrc = Wt + (size_t)(bn * 128 + srow) * K + scs * 8;
    const int sDst = srow * HST + scs * 4;  // u32 offset

    // ldmatrix per-lane byte offsets (within operand slab)
    const uint32_t sbase = (uint32_t)__cvta_generic_to_shared(smem_u);
    const uint32_t aoff =
        ((((lane & 7) + ((lane & 8) ? 8 : 0)) * HST) + ((lane & 16) ? 4 : 0)) * 4;
    const uint32_t boff =
        (((lane & 7) * HST) + ((lane & 8) ? 4 : 0) +
         ((lane & 16) ? 8 * HST : 0)) * 4;

    float acc[4][4][4];
    #pragma unroll
    for (int mi = 0; mi < 4; mi++)
        #pragma unroll
        for (int ni = 0; ni < 4; ni++)
            #pragma unroll
            for (int j = 0; j < 4; j++) acc[mi][ni][j] = 0.f;

    #define ISSUE(stg, kt)                                                     \
        {                                                                      \
            uint32_t* as = smem_u + (stg) * HG_STG;                            \
            uint32_t* bs = as + H_STG_U32;                                     \
            _Pragma("unroll")                                                  \
            for (int i = 0; i < 2; i++) {                                      \
                cp_async16(as + sDst + i * (64 * HST),                         \
                           aSrc + (size_t)(kt) * 32 + (size_t)i * 64 * K);     \
                cp_async16(bs + sDst + i * (64 * HST),                         \
                           bSrc + (size_t)(kt) * 32 + (size_t)i * 64 * K);     \
            }                                                                  \
        }

    const int ntiles = K / 32;
    ISSUE(0, 0); cp_commit();
    ISSUE(1, 1); cp_commit();

    int buf = 0;
    for (int kt = 0; kt < ntiles; kt++) {
        cp_wait<1>();
        __syncthreads();

        if (kt + 2 < ntiles) {
            int nstg = buf + 2; if (nstg >= HNSTAGE) nstg -= HNSTAGE;
            ISSUE(nstg, kt + 2);
        }
        cp_commit();

        // ---- compute on stage `buf` (ldmatrix fragment loads) ----
        {
            const uint32_t abase =
                sbase + (buf * HG_STG + (wm * 64) * HST) * 4 + aoff;
            const uint32_t bbase =
                sbase + (buf * HG_STG + H_STG_U32 + (wn * 32) * HST) * 4 + boff;
            #pragma unroll
            for (int ks = 0; ks < 2; ks++) {
                uint32_t af[4][4], bf[4][2];
                #pragma unroll
                for (int mi = 0; mi < 4; mi++)
                    LDSM_X4(af[mi][0], af[mi][1], af[mi][2], af[mi][3],
                            abase + (mi * 16 * HST + ks * 8) * 4);
                #pragma unroll
                for (int nip = 0; nip < 2; nip++)
                    LDSM_X4(bf[2 * nip][0], bf[2 * nip][1],
                            bf[2 * nip + 1][0], bf[2 * nip + 1][1],
                            bbase + (nip * 16 * HST + ks * 8) * 4);
                #pragma unroll
                for (int mi = 0; mi < 4; mi++)
                    #pragma unroll
                    for (int ni = 0; ni < 4; ni++)
                        mma_f16(acc[mi][ni], af[mi], bf[ni]);
            }
        }

        buf++; if (buf == HNSTAGE) buf = 0;
    }
    #undef ISSUE

    // ---- epilogue ----
    float*  Cf = reinterpret_cast<float*>(Cv);
    __half* Ch = reinterpret_cast<__half*>(Cv);
    const int row_base = bm * 128 + wm * 64;
    const int col_base = bn * 128 + wn * 32;
    #pragma unroll
    for (int mi = 0; mi < 4; mi++) {
        #pragma unroll
        for (int ni = 0; ni < 4; ni++) {
            const int col = col_base + ni * 8 + 2 * q;
            const float b0 = bias[col], b1 = bias[col + 1];
            #pragma unroll
            for (int half_i = 0; half_i < 2; half_i++) {
                const int row = row_base + mi * 16 + g + half_i * 8;
                const size_t base = (size_t)row * N + col;
                float v0 = acc[mi][ni][half_i * 2 + 0] + b0;
                float v1 = acc[mi][ni][half_i * 2 + 1] + b1;
                if (EPI == 1) { v0 += res[base]; v1 += res[base + 1]; }
                if (EPI == 2) {
                    *reinterpret_cast<__half2*>(Ch + base) =
                        __floats2half2_rn(gelu_f(v0), gelu_f(v1));
                } else {
                    *reinterpret_cast<float2*>(Cf + base) = make_float2(v0, v1);
                }
            }
        }
    }
}

// ---------------------------------------------------------------------------
// V transpose: qkv V slice -> vt[bh][d][s], tf32-rounded.        (proven)
// ---------------------------------------------------------------------------
__global__ void __launch_bounds__(256) vtrans_kernel(
    const float* __restrict__ qkv, float* __restrict__ vt)
{
    __shared__ float tile[32][33];
    const int bh = blockIdx.x, b = bh >> 4, h = bh & 15;
    const int s0 = blockIdx.y * 32, d0 = blockIdx.z * 32;
    const int tx = threadIdx.x, ty = threadIdx.y;

    #pragma unroll
    for (int i = 0; i < 4; i++) {
        int s = s0 + ty * 4 + i;
        tile[ty * 4 + i][tx] =
            qkv[((size_t)s * BATCH + b) * (3 * EMB) + 2 * EMB + h * HD + d0 + tx];
    }
    __syncthreads();
    #pragma unroll
    for (int i = 0; i < 4; i++) {
        int d = d0 + ty * 4 + i;
        vt[((size_t)bh * HD + d) * S_LEN + s0 + tx] = tf32r(tile[tx][ty * 4 + i]);
    }
}

// ---------------------------------------------------------------------------
// Flash attention on tensor cores (tf32 m16n8k8), online softmax. (proven)
// Output written as HALF (feeds proj GEMM A operand).
// ---------------------------------------------------------------------------
#define ATS 68
#define ATTN_SMEM_BYTES (3 * 64 * ATS * 4)

__global__ void __launch_bounds__(128) attn_mma_kernel(
    const float* __restrict__ qkv, const float* __restrict__ vt,
    __half* __restrict__ out)
{
    extern __shared__ float sm[];
    float* Ks  = sm;
    float* Vts = sm + 64 * ATS;
    float* Ps  = sm + 2 * 64 * ATS;

    const int bh = blockIdx.x, b = bh >> 4, h = bh & 15;
    const int q0 = blockIdx.y * 64;
    const int t = threadIdx.x, w = t >> 5, lane = t & 31;
    const int g = lane >> 2, q = lane & 3;
    const int wrow = w * 16;

    #pragma unroll
    for (int i = 0; i < 8; i++) {
        int idx = t + i * 128;
        int r = idx >> 4, c = (idx & 15) << 2;
        float4 v = *reinterpret_cast<const float4*>(
            qkv + ((size_t)(q0 + r) * BATCH + b) * (3 * EMB) + h * HD + c);
        v.x = tf32r(v.x); v.y = tf32r(v.y); v.z = tf32r(v.z); v.w = tf32r(v.w);
        *reinterpret_cast<float4*>(&Ks[r * ATS + c]) = v;
    }
    __syncthreads();

    uint32_t qf[8][4];
    #pragma unroll
    for (int kt = 0; kt < 8; kt++) {
        qf[kt][0] = __float_as_uint(Ks[(wrow + g)     * ATS + kt * 8 + q]);
        qf[kt][1] = __float_as_uint(Ks[(wrow + g + 8) * ATS + kt * 8 + q]);
        qf[kt][2] = __float_as_uint(Ks[(wrow + g)     * ATS + kt * 8 + q + 4]);
        qf[kt][3] = __float_as_uint(Ks[(wrow + g + 8) * ATS + kt * 8 + q + 4]);
    }
    __syncthreads();

    float o[8][4];
    #pragma unroll
    for (int nt = 0; nt < 8; nt++)
        #pragma unroll
        for (int j = 0; j < 4; j++) o[nt][j] = 0.f;
    float m0 = -1e30f, m1 = -1e30f, l0 = 0.f, l1 = 0.f;

    for (int kv0 = 0; kv0 < S_LEN; kv0 += 64) {
        #pragma unroll
        for (int i = 0; i < 8; i++) {
            int idx = t + i * 128;
            int r = idx >> 4, c = (idx & 15) << 2;
            float4 kv4 = *reinterpret_cast<const float4*>(
                qkv + ((size_t)(kv0 + r) * BATCH + b) * (3 * EMB) + EMB + h * HD + c);
            kv4.x = tf32r(kv4.x); kv4.y = tf32r(kv4.y);
            kv4.z = tf32r(kv4.z); kv4.w = tf32r(kv4.w);
            *reinterpret_cast<float4*>(&Ks[r * ATS + c]) = kv4;
            float4 vv4 = *reinterpret_cast<const float4*>(
                vt + ((size_t)bh * HD + r) * S_LEN + kv0 + c);
            *reinterpret_cast<float4*>(&Vts[r * ATS + c]) = vv4;
        }
        __syncthreads();

        float sc[8][4];
        #pragma unroll
        for (int nt = 0; nt < 8; nt++) {
            sc[nt][0] = sc[nt][1] = sc[nt][2] = sc[nt][3] = 0.f;
            #pragma unroll
            for (int kt = 0; kt < 8; kt++) {
                uint32_t bfr[2];
                bfr[0] = __float_as_uint(Ks[(nt * 8 + g) * ATS + kt * 8 + q]);
                bfr[1] = __float_as_uint(Ks[(nt * 8 + g) * ATS + kt * 8 + q + 4]);
                mma_tf32(sc[nt], qf[kt], bfr);
            }
        }

        float mx0 = -1e30f, mx1 = -1e30f;
        #pragma unroll
        for (int nt = 0; nt < 8; nt++) {
            sc[nt][0] *= 0.125f; sc[nt][1] *= 0.125f;
            sc[nt][2] *= 0.125f; sc[nt][3] *= 0.125f;
            mx0 = fmaxf(mx0, fmaxf(sc[nt][0], sc[nt][1]));
            mx1 = fmaxf(mx1, fmaxf(sc[nt][2], sc[nt][3]));
        }
        mx0 = fmaxf(mx0, __shfl_xor_sync(0xffffffffu, mx0, 1));
        mx0 = fmaxf(mx0, __shfl_xor_sync(0xffffffffu, mx0, 2));
        mx1 = fmaxf(mx1, __shfl_xor_sync(0xffffffffu, mx1, 1));
        mx1 = fmaxf(mx1, __shfl_xor_sync(0xffffffffu, mx1, 2));

        const float mn0 = fmaxf(m0, mx0), mn1 = fmaxf(m1, mx1);
        const float a0 = __expf(m0 - mn0), a1 = __expf(m1 - mn1);
        float s0 = 0.f, s1 = 0.f;
        #pragma unroll
        for (int nt = 0; nt < 8; nt++) {
            float p0 = __expf(sc[nt][0] - mn0);
            float p1 = __expf(sc[nt][1] - mn0);
            float p2 = __expf(sc[nt][2] - mn1);
            float p3 = __expf(sc[nt][3] - mn1);
            s0 += p0 + p1; s1 += p2 + p3;
            *reinterpret_cast<float2*>(&Ps[(wrow + g) * ATS + nt * 8 + 2 * q]) =
                make_float2(tf32r(p0), tf32r(p1));
            *reinterpret_cast<float2*>(&Ps[(wrow + g + 8) * ATS + nt * 8 + 2 * q]) =
                make_float2(tf32r(p2), tf32r(p3));
        }
        s0 += __shfl_xor_sync(0xffffffffu, s0, 1);
        s0 += __shfl_xor_sync(0xffffffffu, s0, 2);
        s1 += __shfl_xor_sync(0xffffffffu, s1, 1);
        s1 += __shfl_xor_sync(0xffffffffu, s1, 2);

        l0 = l0 * a0 + s0; l1 = l1 * a1 + s1;
        m0 = mn0; m1 = mn1;
        #pragma unroll
        for (int nt = 0; nt < 8; nt++) {
            o[nt][0] *= a0; o[nt][1] *= a0;
            o[nt][2] *= a1; o[nt][3] *= a1;
        }
        __syncwarp();

        #pragma unroll
        for (int kt = 0; kt < 8; kt++) {
            uint32_t af[4];
            af[0] = __float_as_uint(Ps[(wrow + g)     * ATS + kt * 8 + q]);
            af[1] = __float_as_uint(Ps[(wrow + g + 8) * ATS + kt * 8 + q]);
            af[2] = __float_as_uint(Ps[(wrow + g)     * ATS + kt * 8 + q + 4]);
            af[3] = __float_as_uint(Ps[(wrow + g + 8) * ATS + kt * 8 + q + 4]);
            #pragma unroll
            for (int nt = 0; nt < 8; nt++) {
                uint32_t bfr[2];
                bfr[0] = __float_as_uint(Vts[(nt * 8 + g) * ATS + kt * 8 + q]);
                bfr[1] = __float_as_uint(Vts[(nt * 8 + g) * ATS + kt * 8 + q + 4]);
                mma_tf32(o[nt], af, bfr);
            }
        }
        __syncthreads();
    }

    const float inv0 = 1.0f / l0, inv1 = 1.0f / l1;
    const int s_row0 = q0 + wrow + g;
    #pragma unroll
    for (int nt = 0; nt < 8; nt++) {
        const int col = h * HD + nt * 8 + 2 * q;
        *reinterpret_cast<__half2*>(
            out + ((size_t)s_row0 * BATCH + b) * EMB + col) =
            __floats2half2_rn(o[nt][0] * inv0, o[nt][1] * inv0);
        *reinterpret_cast<__half2*>(
            out + ((size_t)(s_row0 + 8) * BATCH + b) * EMB + col) =
            __floats2half2_rn(o[nt][2] * inv1, o[nt][3] * inv1);
    }
}

// ---------------------------------------------------------------------------
// Launch
// ---------------------------------------------------------------------------
extern "C" void kernel_launch(void* const* d_in, const int* in_sizes, int n_in,
                              void* d_out, int out_size)
{
    const float* x      = (const float*)d_in[0];
    const float* ln1_g  = (const float*)d_in[1];
    const float* ln1_b  = (const float*)d_in[2];
    const float* w_attn = (const float*)d_in[3];
    const float* b_attn = (const float*)d_in[4];
    const float* w_proj = (const float*)d_in[5];
    const float* b_proj = (const float*)d_in[6];
    const float* ln2_g  = (const float*)d_in[7];
    const float* ln2_b  = (const float*)d_in[8];
    const float* w_fc   = (const float*)d_in[9];
    const float* b_fc   = (const float*)d_in[10];
    const float* w_out  = (const float*)d_in[11];
    const float* b_out  = (const float*)d_in[12];
    float* out = (float*)d_out;

    void *p_h, *p_qkv, *p_a, *p_x2, *p_m, *p_wt, *p_vt;
    cudaGetSymbolAddress(&p_h,   g_h);
    cudaGetSymbolAddress(&p_qkv, g_qkv);
    cudaGetSymbolAddress(&p_a,   g_a);
    cudaGetSymbolAddress(&p_x2,  g_x2);
    cudaGetSymbolAddress(&p_m,   g_m);
    cudaGetSymbolAddress(&p_wt,  g_wt);
    cudaGetSymbolAddress(&p_vt,  g_vt);
    __half* h   = (__half*)p_h;
    float*  qkv = (float*)p_qkv;
    __half* a   = (__half*)p_a;
    float*  x2  = (float*)p_x2;
    __half* mm  = (__half*)p_m;
    __half* wt  = (__half*)p_wt;
    float*  vt  = (float*)p_vt;

    __half* wt_attn = wt;                       // [3E][E]
    __half* wt_proj = wt + 3 * EMB * EMB;       // [E][E]
    __half* wt_fc   = wt + 4 * EMB * EMB;       // [4E][E]
    __half* wt_out  = wt + 8 * EMB * EMB;       // [E][4E]

    cudaFuncSetAttribute(attn_mma_kernel,
                         cudaFuncAttributeMaxDynamicSharedMemorySize,
                         ATTN_SMEM_BYTES);
    cudaFuncSetAttribute(gemm_f16<0>,
                         cudaFuncAttributeMaxDynamicSharedMemorySize,
                         GEMM_SMEM_BYTES);
    cudaFuncSetAttribute(gemm_f16<1>,
                         cudaFuncAttributeMaxDynamicSharedMemorySize,
                         GEMM_SMEM_BYTES);
    cudaFuncSetAttribute(gemm_f16<2>,
                         cudaFuncAttributeMaxDynamicSharedMemorySize,
                         GEMM_SMEM_BYTES);

    // 0. transpose+convert weights to half [N][K]
    wtrans_kernel<<<dim3(3 * EMB / 32, EMB / 32), dim3(32, 8)>>>(
        w_attn, wt_attn, EMB, 3 * EMB);
    wtrans_kernel<<<dim3(EMB / 32, EMB / 32), dim3(32, 8)>>>(
        w_proj, wt_proj, EMB, EMB);
    wtrans_kernel<<<dim3(4 * EMB / 32, EMB / 32), dim3(32, 8)>>>(
        w_fc, wt_fc, EMB, 4 * EMB);
    wtrans_kernel<<<dim3(EMB / 32, 4 * EMB / 32), dim3(32, 8)>>>(
        w_out, wt_out, 4 * EMB, EMB);

    // 1. ln1 (half output)
    ln_kernel<<<NTOK, 256>>>(x, ln1_g, ln1_b, h);
    // 2. qkv = h @ w_attn + b_attn            [4096, 3072] fp32 out
    gemm_f16<0><<<dim3(3 * EMB / 128, NTOK / 128), 256, GEMM_SMEM_BYTES>>>(
        NTOK, 3 * EMB, EMB, h, wt_attn, b_attn, nullptr, qkv);
    // 3a. V transpose for tensor-core PV
    vtrans_kernel<<<dim3(NH * BATCH, S_LEN / 32, HD / 32), dim3(32, 8)>>>(qkv, vt);
    // 3b. attention -> a (half, merged heads, token layout)
    attn_mma_kernel<<<dim3(BATCH * NH, S_LEN / 64), 128, ATTN_SMEM_BYTES>>>(
        qkv, vt, a);
    // 4. x2 = x + a @ w_proj + b_proj         fp32 out
    gemm_f16<1><<<dim3(EMB / 128, NTOK / 128), 256, GEMM_SMEM_BYTES>>>(
        NTOK, EMB, EMB, a, wt_proj, b_proj, x, x2);
    // 5. ln2 (half output)
    ln_kernel<<<NTOK, 256>>>(x2, ln2_g, ln2_b, h);
    // 6. m = gelu(h @ w_fc + b_fc)            [4096, 4096] half out
    gemm_f16<2><<<dim3(4 * EMB / 128, NTOK / 128), 256, GEMM_SMEM_BYTES>>>(
        NTOK, 4 * EMB, EMB, h, wt_fc, b_fc, nullptr, mm);
    // 7. out = x2 + m @ w_out + b_out         fp32 out
    gemm_f16<1><<<dim3(EMB / 128, NTOK / 128), 256, GEMM_SMEM_BYTES>>>(
        NTOK, EMB, 4 * EMB, mm, wt_out, b_out, x2, out);
}

// round 15
// speedup vs baseline: 2.0033x; 1.1584x over previous
#include <cuda_runtime.h>
#include <cuda_fp16.h>
#include <math.h>
#include <stdint.h>

// ---------------------------------------------------------------------------
// Problem constants
// ---------------------------------------------------------------------------
#define S_LEN 1024
#define BATCH 4
#define EMB   1024
#define NH    16
#define HD    64
#define NTOK  (S_LEN * BATCH)
#define LN_EPS 1e-5f

// ---------------------------------------------------------------------------
// Scratch (device globals -- allocation-free kernel_launch requirement)
// ---------------------------------------------------------------------------
__device__ __half g_h  [NTOK * EMB];          // ln output (half)
__device__ __half g_qkv[NTOK * 3 * EMB];      // qkv (half)
__device__ __half g_a  [NTOK * EMB];          // attn out (half)
__device__ float  g_x2 [NTOK * EMB];          // x + attn residual (fp32)
__device__ __half g_m  [NTOK * 4 * EMB];      // gelu out (half)
__device__ __half g_wt [12 * EMB * EMB];      // transposed half weights [N][K]
__device__ __half g_vt [NH * BATCH * HD * S_LEN];  // V transposed (half)

// ---------------------------------------------------------------------------
// helpers
// ---------------------------------------------------------------------------
// fp16 mma: m16n8k16, fp32 accumulate
__device__ __forceinline__ void mma_f16(
    float c[4], const uint32_t a[4], const uint32_t b[2])
{
    asm volatile(
        "mma.sync.aligned.m16n8k16.row.col.f32.f16.f16.f32 "
        "{%0,%1,%2,%3}, {%4,%5,%6,%7}, {%8,%9}, {%0,%1,%2,%3};\n"
        : "+f"(c[0]), "+f"(c[1]), "+f"(c[2]), "+f"(c[3])
        : "r"(a[0]), "r"(a[1]), "r"(a[2]), "r"(a[3]),
          "r"(b[0]), "r"(b[1]));
}

// ldmatrix x4 (b16): 4 8x8 tiles, per-lane row addresses
#define LDSM_X4(r0, r1, r2, r3, addr)                                          \
    asm volatile(                                                              \
        "ldmatrix.sync.aligned.m8n8.x4.shared.b16 {%0,%1,%2,%3}, [%4];"        \
        : "=r"(r0), "=r"(r1), "=r"(r2), "=r"(r3) : "r"(addr))

// cp.async helpers
__device__ __forceinline__ void cp_async16(void* smem_ptr, const void* gptr) {
    uint32_t s = (uint32_t)__cvta_generic_to_shared(smem_ptr);
    asm volatile("cp.async.cg.shared.global [%0], [%1], 16;\n"
                 :: "r"(s), "l"(gptr));
}
__device__ __forceinline__ void cp_commit() {
    asm volatile("cp.async.commit_group;\n");
}
template <int N>
__device__ __forceinline__ void cp_wait() {
    asm volatile("cp.async.wait_group %0;\n" :: "n"(N));
}

// ---------------------------------------------------------------------------
// Weight transpose+convert: src [K][N] fp32 -> dst [N][K] half   (proven)
// ---------------------------------------------------------------------------
__global__ void __launch_bounds__(256) wtrans_kernel(
    const float* __restrict__ src, __half* __restrict__ dst, int K, int N)
{
    __shared__ float tile[32][33];
    const int n0 = blockIdx.x * 32, k0 = blockIdx.y * 32;
    const int tx = threadIdx.x, ty = threadIdx.y;

    #pragma unroll
    for (int i = 0; i < 4; i++) {
        int k = k0 + ty * 4 + i;
        tile[ty * 4 + i][tx] = src[(size_t)k * N + n0 + tx];
    }
    __syncthreads();
    #pragma unroll
    for (int i = 0; i < 4; i++) {
        int n = n0 + ty * 4 + i;
        dst[(size_t)n * K + k0 + tx] = __float2half_rn(tile[tx][ty * 4 + i]);
    }
}

// ---------------------------------------------------------------------------
// LayerNorm (writes half: only ever feeds GEMM A-operands)       (proven)
// ---------------------------------------------------------------------------
__global__ void __launch_bounds__(256) ln_kernel(
    const float* __restrict__ x, const float* __restrict__ gamma,
    const float* __restrict__ beta, __half* __restrict__ out)
{
    const int row = blockIdx.x;
    const int t   = threadIdx.x;
    const float4* xr = reinterpret_cast<const float4*>(x + (size_t)row * EMB);
    float4 v = xr[t];

    float s  = v.x + v.y + v.z + v.w;
    float sq = v.x * v.x + v.y * v.y + v.z * v.z + v.w * v.w;
    #pragma unroll
    for (int m = 16; m > 0; m >>= 1) {
        s  += __shfl_xor_sync(0xffffffffu, s,  m);
        sq += __shfl_xor_sync(0xffffffffu, sq, m);
    }

    __shared__ float sh_s[8], sh_q[8];
    __shared__ float sh_mean, sh_rstd;
    const int warp = t >> 5, lane = t & 31;
    if (lane == 0) { sh_s[warp] = s; sh_q[warp] = sq; }
    __syncthreads();
    if (t == 0) {
        float ts = 0.f, tq = 0.f;
        #pragma unroll
        for (int i = 0; i < 8; i++) { ts += sh_s[i]; tq += sh_q[i]; }
        float mean = ts * (1.0f / EMB);
        float var  = tq * (1.0f / EMB) - mean * mean;
        sh_mean = mean;
        sh_rstd = rsqrtf(var + LN_EPS);
    }
    __syncthreads();
    const float mean = sh_mean, rstd = sh_rstd;

    float4 g4 = reinterpret_cast<const float4*>(gamma)[t];
    float4 b4 = reinterpret_cast<const float4*>(beta)[t];
    __half2 h01 = __floats2half2_rn((v.x - mean) * rstd * g4.x + b4.x,
                                    (v.y - mean) * rstd * g4.y + b4.y);
    __half2 h23 = __floats2half2_rn((v.z - mean) * rstd * g4.z + b4.z,
                                    (v.w - mean) * rstd * g4.w + b4.w);
    __half2* o = reinterpret_cast<__half2*>(out + (size_t)row * EMB + t * 4);
    o[0] = h01; o[1] = h23;
}

// ---------------------------------------------------------------------------
// GELU (GPT-2 tanh approximation)
// ---------------------------------------------------------------------------
__device__ __forceinline__ float gelu_f(float x) {
    const float c = 0.7978845608028654f;
    float x3 = x * x * x;
    return 0.5f * x * (1.0f + tanhf(c * (x + 0.044715f * x3)));
}

// ---------------------------------------------------------------------------
// FP16 tensor-core GEMM, cp.async 3-stage pipeline, LDMATRIX fragment loads.
//   C[M,N] = A[M,K] @ Wt[N,K]^T + bias
//   EPI 0: bias -> HALF out   1: bias+res -> fp32 out   2: gelu -> half out
// (R13, proven; EPI 0 output dtype changed fp32->half for the qkv path)
// ---------------------------------------------------------------------------
#define HST 20                            // row stride in u32 (40 halves)
#define H_STG_U32  (128 * HST)            // 2560 u32 per operand per stage
#define HG_STG (2 * H_STG_U32)            // 5120 u32 = 20480 B per stage
#define HNSTAGE 3
#define GEMM_SMEM_BYTES (HNSTAGE * HG_STG * 4)   // 61440 B

template <int EPI>
__global__ void __launch_bounds__(256, 2) gemm_f16(
    int M, int N, int K,
    const __half* __restrict__ A, const __half* __restrict__ Wt,
    const float* __restrict__ bias, const float* __restrict__ res,
    void* __restrict__ Cv)
{
    extern __shared__ uint32_t smem_u[];

    const int bm = blockIdx.y, bn = blockIdx.x;
    const int t    = threadIdx.x;
    const int warp = t >> 5, lane = t & 31;
    const int wm = warp >> 2;               // 0..1 : 64-row slab
    const int wn = warp & 3;                // 0..3 : 32-col slab
    const int g  = lane >> 2;               // 0..7
    const int q  = lane & 3;                // 0..3

    const int srow = t >> 2;
    const int scs  = t & 3;
    const __half* aSrc = A  + (size_t)(bm * 128 + srow) * K + scs * 8;
    const __half* bSrc = Wt + (size_t)(bn * 128 + srow) * K + scs * 8;
    const int sDst = srow * HST + scs * 4;

    const uint32_t sbase = (uint32_t)__cvta_generic_to_shared(smem_u);
    const uint32_t aoff =
        ((((lane & 7) + ((lane & 8) ? 8 : 0)) * HST) + ((lane & 16) ? 4 : 0)) * 4;
    const uint32_t boff =
        (((lane & 7) * HST) + ((lane & 8) ? 4 : 0) +
         ((lane & 16) ? 8 * HST : 0)) * 4;

    float acc[4][4][4];
    #pragma unroll
    for (int mi = 0; mi < 4; mi++)
        #pragma unroll
        for (int ni = 0; ni < 4; ni++)
            #pragma unroll
            for (int j = 0; j < 4; j++) acc[mi][ni][j] = 0.f;

    #define ISSUE(stg, kt)                                                     \
        {                                                                      \
            uint32_t* as = smem_u + (stg) * HG_STG;                            \
            uint32_t* bs = as + H_STG_U32;                                     \
            _Pragma("unroll")                                                  \
            for (int i = 0; i < 2; i++) {                                      \
                cp_async16(as + sDst + i * (64 * HST),                         \
                           aSrc + (size_t)(kt) * 32 + (size_t)i * 64 * K);     \
                cp_async16(bs + sDst + i * (64 * HST),                         \
                           bSrc + (size_t)(kt) * 32 + (size_t)i * 64 * K);     \
            }                                                                  \
        }

    const int ntiles = K / 32;
    ISSUE(0, 0); cp_commit();
    ISSUE(1, 1); cp_commit();

    int buf = 0;
    for (int kt = 0; kt < ntiles; kt++) {
        cp_wait<1>();
        __syncthreads();

        if (kt + 2 < ntiles) {
            int nstg = buf + 2; if (nstg >= HNSTAGE) nstg -= HNSTAGE;
            ISSUE(nstg, kt + 2);
        }
        cp_commit();

        {
            const uint32_t abase =
                sbase + (buf * HG_STG + (wm * 64) * HST) * 4 + aoff;
            const uint32_t bbase =
                sbase + (buf * HG_STG + H_STG_U32 + (wn * 32) * HST) * 4 + boff;
            #pragma unroll
            for (int ks = 0; ks < 2; ks++) {
                uint32_t af[4][4], bf[4][2];
                #pragma unroll
                for (int mi = 0; mi < 4; mi++)
                    LDSM_X4(af[mi][0], af[mi][1], af[mi][2], af[mi][3],
                            abase + (mi * 16 * HST + ks * 8) * 4);
                #pragma unroll
                for (int nip = 0; nip < 2; nip++)
                    LDSM_X4(bf[2 * nip][0], bf[2 * nip][1],
                            bf[2 * nip + 1][0], bf[2 * nip + 1][1],
                            bbase + (nip * 16 * HST + ks * 8) * 4);
                #pragma unroll
                for (int mi = 0; mi < 4; mi++)
                    #pragma unroll
                    for (int ni = 0; ni < 4; ni++)
                        mma_f16(acc[mi][ni], af[mi], bf[ni]);
            }
        }

        buf++; if (buf == HNSTAGE) buf = 0;
    }
    #undef ISSUE

    // ---- epilogue ----
    float*  Cf = reinterpret_cast<float*>(Cv);
    __half* Ch = reinterpret_cast<__half*>(Cv);
    const int row_base = bm * 128 + wm * 64;
    const int col_base = bn * 128 + wn * 32;
    #pragma unroll
    for (int mi = 0; mi < 4; mi++) {
        #pragma unroll
        for (int ni = 0; ni < 4; ni++) {
            const int col = col_base + ni * 8 + 2 * q;
            const float b0 = bias[col], b1 = bias[col + 1];
            #pragma unroll
            for (int half_i = 0; half_i < 2; half_i++) {
                const int row = row_base + mi * 16 + g + half_i * 8;
                const size_t base = (size_t)row * N + col;
                float v0 = acc[mi][ni][half_i * 2 + 0] + b0;
                float v1 = acc[mi][ni][half_i * 2 + 1] + b1;
                if (EPI == 1) {
                    v0 += res[base]; v1 += res[base + 1];
                    *reinterpret_cast<float2*>(Cf + base) = make_float2(v0, v1);
                } else if (EPI == 2) {
                    *reinterpret_cast<__half2*>(Ch + base) =
                        __floats2half2_rn(gelu_f(v0), gelu_f(v1));
                } else {
                    *reinterpret_cast<__half2*>(Ch + base) =
                        __floats2half2_rn(v0, v1);
                }
            }
        }
    }
}

// ---------------------------------------------------------------------------
// V transpose: qkv V slice (half) -> vt[bh][d][s] (half)
// ---------------------------------------------------------------------------
__global__ void __launch_bounds__(256) vtrans_kernel(
    const __half* __restrict__ qkv, __half* __restrict__ vt)
{
    __shared__ __half tile[32][36];
    const int bh = blockIdx.x, b = bh >> 4, h = bh & 15;
    const int s0 = blockIdx.y * 32, d0 = blockIdx.z * 32;
    const int tx = threadIdx.x, ty = threadIdx.y;

    #pragma unroll
    for (int i = 0; i < 4; i++) {
        int s = s0 + ty * 4 + i;
        tile[ty * 4 + i][tx] =
            qkv[((size_t)s * BATCH + b) * (3 * EMB) + 2 * EMB + h * HD + d0 + tx];
    }
    __syncthreads();
    #pragma unroll
    for (int i = 0; i < 4; i++) {
        int d = d0 + ty * 4 + i;
        vt[((size_t)bh * HD + d) * S_LEN + s0 + tx] = tile[tx][ty * 4 + i];
    }
}

// ---------------------------------------------------------------------------
// Flash attention, fp16 mma m16n8k16 + ldmatrix, online softmax (fp32).
// Block = (b,h) x 64-row q tile; 4 warps, each owns 16 q rows.
// Tiles in smem as half [64][72] (row stride 36 u32 -- same conflict-free
// fragment bank math as the proven GEMM layout).
// ---------------------------------------------------------------------------
#define ATSH 72                            // halves per row
#define ATRB (ATSH * 2)                    // row stride bytes (144)
#define ATTN_SMEM_BYTES (4 * 64 * ATSH * 2)   // Qs,Ks,Vts,Ps = 36864 B

__global__ void __launch_bounds__(128) attn_mma_kernel(
    const __half* __restrict__ qkv, const __half* __restrict__ vt,
    __half* __restrict__ out)
{
    extern __shared__ __half smh[];
    __half* Qs  = smh;                  // [64][ATSH]
    __half* Ks  = smh + 64 * ATSH;
    __half* Vts = smh + 2 * 64 * ATSH;
    __half* Ps  = smh + 3 * 64 * ATSH;

    const int bh = blockIdx.x, b = bh >> 4, h = bh & 15;
    const int q0 = blockIdx.y * 64;
    const int t = threadIdx.x, w = t >> 5, lane = t & 31;
    const int g = lane >> 2, q = lane & 3;
    const int wrow = w * 16;

    // fragment lane offsets (bytes), identical pattern to GEMM (HST->36)
    const uint32_t aoff =
        (((lane & 7) + ((lane & 8) ? 8 : 0)) * ATRB) + ((lane & 16) ? 16 : 0);
    const uint32_t boff =
        ((lane & 7) * ATRB) + ((lane & 8) ? 16 : 0) +
        ((lane & 16) ? 8 * ATRB : 0);

    const uint32_t qsm = (uint32_t)__cvta_generic_to_shared(Qs);
    const uint32_t ksm = (uint32_t)__cvta_generic_to_shared(Ks);
    const uint32_t vsm = (uint32_t)__cvta_generic_to_shared(Vts);
    const uint32_t psm = (uint32_t)__cvta_generic_to_shared(Ps);

    // ---- stage Q tile (64 x 64 half), 4 x 16B per thread ----
    #pragma unroll
    for (int i = 0; i < 4; i++) {
        int idx = t + i * 128;
        int r = idx >> 3, c = idx & 7;
        uint4 v = *reinterpret_cast<const uint4*>(
            qkv + ((size_t)(q0 + r) * BATCH + b) * (3 * EMB) + h * HD + c * 8);
        *reinterpret_cast<uint4*>(Qs + r * ATSH + c * 8) = v;
    }
    __syncthreads();

    // ---- Q fragments in registers for the whole KV loop ----
    uint32_t qf[4][4];
    {
        const uint32_t qbase = qsm + wrow * ATRB + aoff;
        #pragma unroll
        for (int ks = 0; ks < 4; ks++)
            LDSM_X4(qf[ks][0], qf[ks][1], qf[ks][2], qf[ks][3],
                    qbase + ks * 32);
    }
    __syncthreads();

    float o[8][4];
    #pragma unroll
    for (int nt = 0; nt < 8; nt++)
        #pragma unroll
        for (int j = 0; j < 4; j++) o[nt][j] = 0.f;
    float m0 = -1e30f, m1 = -1e30f, l0 = 0.f, l1 = 0.f;

    for (int kv0 = 0; kv0 < S_LEN; kv0 += 64) {
        // ---- stage K (rows=kv, cols=d) and Vt (rows=d, cols=kv) ----
        #pragma unroll
        for (int i = 0; i < 4; i++) {
            int idx = t + i * 128;
            int r = idx >> 3, c = idx & 7;
            uint4 kvv = *reinterpret_cast<const uint4*>(
                qkv + ((size_t)(kv0 + r) * BATCH + b) * (3 * EMB) + EMB
                    + h * HD + c * 8);
            *reinterpret_cast<uint4*>(Ks + r * ATSH + c * 8) = kvv;
            uint4 vv = *reinterpret_cast<const uint4*>(
                vt + ((size_t)bh * HD + r) * S_LEN + kv0 + c * 8);
            *reinterpret_cast<uint4*>(Vts + r * ATSH + c * 8) = vv;
        }
        __syncthreads();

        // ---- scores: S[16][64] = Q[16][64] @ K[64][64]^T ----
        float sc[8][4];
        #pragma unroll
        for (int nt = 0; nt < 8; nt++)
            #pragma unroll
            for (int j = 0; j < 4; j++) sc[nt][j] = 0.f;

        #pragma unroll
        for (int ks = 0; ks < 4; ks++) {
            uint32_t bf[8][2];
            #pragma unroll
            for (int nip = 0; nip < 4; nip++)
                LDSM_X4(bf[2 * nip][0], bf[2 * nip][1],
                        bf[2 * nip + 1][0], bf[2 * nip + 1][1],
                        ksm + boff + nip * 16 * ATRB + ks * 32);
            #pragma unroll
            for (int nt = 0; nt < 8; nt++)
                mma_f16(sc[nt], qf[ks], bf[nt]);
        }

        // ---- online softmax (rows g and g+8; quad shfl over 64 cols) ----
        float mx0 = -1e30f, mx1 = -1e30f;
        #pragma unroll
        for (int nt = 0; nt < 8; nt++) {
            sc[nt][0] *= 0.125f; sc[nt][1] *= 0.125f;
            sc[nt][2] *= 0.125f; sc[nt][3] *= 0.125f;
            mx0 = fmaxf(mx0, fmaxf(sc[nt][0], sc[nt][1]));
            mx1 = fmaxf(mx1, fmaxf(sc[nt][2], sc[nt][3]));
        }
        mx0 = fmaxf(mx0, __shfl_xor_sync(0xffffffffu, mx0, 1));
        mx0 = fmaxf(mx0, __shfl_xor_sync(0xffffffffu, mx0, 2));
        mx1 = fmaxf(mx1, __shfl_xor_sync(0xffffffffu, mx1, 1));
        mx1 = fmaxf(mx1, __shfl_xor_sync(0xffffffffu, mx1, 2));

        const float mn0 = fmaxf(m0, mx0), mn1 = fmaxf(m1, mx1);
        const float a0 = __expf(m0 - mn0), a1 = __expf(m1 - mn1);
        float s0 = 0.f, s1 = 0.f;
        #pragma unroll
        for (int nt = 0; nt < 8; nt++) {
            float p0 = __expf(sc[nt][0] - mn0);
            float p1 = __expf(sc[nt][1] - mn0);
            float p2 = __expf(sc[nt][2] - mn1);
            float p3 = __expf(sc[nt][3] - mn1);
            s0 += p0 + p1; s1 += p2 + p3;
            *reinterpret_cast<__half2*>(
                Ps + (wrow + g) * ATSH + nt * 8 + 2 * q) =
                __floats2half2_rn(p0, p1);
            *reinterpret_cast<__half2*>(
                Ps + (wrow + g + 8) * ATSH + nt * 8 + 2 * q) =
                __floats2half2_rn(p2, p3);
        }
        s0 += __shfl_xor_sync(0xffffffffu, s0, 1);
        s0 += __shfl_xor_sync(0xffffffffu, s0, 2);
        s1 += __shfl_xor_sync(0xffffffffu, s1, 1);
        s1 += __shfl_xor_sync(0xffffffffu, s1, 2);

        l0 = l0 * a0 + s0; l1 = l1 * a1 + s1;
        m0 = mn0; m1 = mn1;
        #pragma unroll
        for (int nt = 0; nt < 8; nt++) {
            o[nt][0] *= a0; o[nt][1] *= a0;
            o[nt][2] *= a1; o[nt][3] *= a1;
        }
        __syncwarp();   // Ps produced+consumed within this warp

        // ---- PV: O[16][64] += P[16][64] @ Vt[64][64]^T ----
        #pragma unroll
        for (int ks = 0; ks < 4; ks++) {
            uint32_t af[4];
            LDSM_X4(af[0], af[1], af[2], af[3],
                    psm + wrow * ATRB + aoff + ks * 32);
            uint32_t bf[8][2];
            #pragma unroll
            for (int nip = 0; nip < 4; nip++)
                LDSM_X4(bf[2 * nip][0], bf[2 * nip][1],
                        bf[2 * nip + 1][0], bf[2 * nip + 1][1],
                        vsm + boff + nip * 16 * ATRB + ks * 32);
            #pragma unroll
            for (int nt = 0; nt < 8; nt++)
                mma_f16(o[nt], af, bf[nt]);
        }
        __syncthreads();   // protect Ks/Vts before next iteration
    }

    // ---- finalize: divide by l, store half ----
    const float inv0 = 1.0f / l0, inv1 = 1.0f / l1;
    const int s_row0 = q0 + wrow + g;
    #pragma unroll
    for (int nt = 0; nt < 8; nt++) {
        const int col = h * HD + nt * 8 + 2 * q;
        *reinterpret_cast<__half2*>(
            out + ((size_t)s_row0 * BATCH + b) * EMB + col) =
            __floats2half2_rn(o[nt][0] * inv0, o[nt][1] * inv0);
        *reinterpret_cast<__half2*>(
            out + ((size_t)(s_row0 + 8) * BATCH + b) * EMB + col) =
            __floats2half2_rn(o[nt][2] * inv1, o[nt][3] * inv1);
    }
}

// ---------------------------------------------------------------------------
// Launch
// ---------------------------------------------------------------------------
extern "C" void kernel_launch(void* const* d_in, const int* in_sizes, int n_in,
                              void* d_out, int out_size)
{
    const float* x      = (const float*)d_in[0];
    const float* ln1_g  = (const float*)d_in[1];
    const float* ln1_b  = (const float*)d_in[2];
    const float* w_attn = (const float*)d_in[3];
    const float* b_attn = (const float*)d_in[4];
    const float* w_proj = (const float*)d_in[5];
    const float* b_proj = (const float*)d_in[6];
    const float* ln2_g  = (const float*)d_in[7];
    const float* ln2_b  = (const float*)d_in[8];
    const float* w_fc   = (const float*)d_in[9];
    const float* b_fc   = (const float*)d_in[10];
    const float* w_out  = (const float*)d_in[11];
    const float* b_out  = (const float*)d_in[12];
    float* out = (float*)d_out;

    void *p_h, *p_qkv, *p_a, *p_x2, *p_m, *p_wt, *p_vt;
    cudaGetSymbolAddress(&p_h,   g_h);
    cudaGetSymbolAddress(&p_qkv, g_qkv);
    cudaGetSymbolAddress(&p_a,   g_a);
    cudaGetSymbolAddress(&p_x2,  g_x2);
    cudaGetSymbolAddress(&p_m,   g_m);
    cudaGetSymbolAddress(&p_wt,  g_wt);
    cudaGetSymbolAddress(&p_vt,  g_vt);
    __half* h   = (__half*)p_h;
    __half* qkv = (__half*)p_qkv;
    __half* a   = (__half*)p_a;
    float*  x2  = (float*)p_x2;
    __half* mm  = (__half*)p_m;
    __half* wt  = (__half*)p_wt;
    __half* vt  = (__half*)p_vt;

    __half* wt_attn = wt;                       // [3E][E]
    __half* wt_proj = wt + 3 * EMB * EMB;       // [E][E]
    __half* wt_fc   = wt + 4 * EMB * EMB;       // [4E][E]
    __half* wt_out  = wt + 8 * EMB * EMB;       // [E][4E]

    cudaFuncSetAttribute(attn_mma_kernel,
                         cudaFuncAttributeMaxDynamicSharedMemorySize,
                         ATTN_SMEM_BYTES);
    cudaFuncSetAttribute(gemm_f16<0>,
                         cudaFuncAttributeMaxDynamicSharedMemorySize,
                         GEMM_SMEM_BYTES);
    cudaFuncSetAttribute(gemm_f16<1>,
                         cudaFuncAttributeMaxDynamicSharedMemorySize,
                         GEMM_SMEM_BYTES);
    cudaFuncSetAttribute(gemm_f16<2>,
                         cudaFuncAttributeMaxDynamicSharedMemorySize,
                         GEMM_SMEM_BYTES);

    // 0. transpose+convert weights to half [N][K]
    wtrans_kernel<<<dim3(3 * EMB / 32, EMB / 32), dim3(32, 8)>>>(
        w_attn, wt_attn, EMB, 3 * EMB);
    wtrans_kernel<<<dim3(EMB / 32, EMB / 32), dim3(32, 8)>>>(
        w_proj, wt_proj, EMB, EMB);
    wtrans_kernel<<<dim3(4 * EMB / 32, EMB / 32), dim3(32, 8)>>>(
        w_fc, wt_fc, EMB, 4 * EMB);
    wtrans_kernel<<<dim3(EMB / 32, 4 * EMB / 32), dim3(32, 8)>>>(
        w_out, wt_out, 4 * EMB, EMB);

    // 1. ln1 (half output)
    ln_kernel<<<NTOK, 256>>>(x, ln1_g, ln1_b, h);
    // 2. qkv = h @ w_attn + b_attn            [4096, 3072] HALF out
    gemm_f16<0><<<dim3(3 * EMB / 128, NTOK / 128), 256, GEMM_SMEM_BYTES>>>(
        NTOK, 3 * EMB, EMB, h, wt_attn, b_attn, nullptr, qkv);
    // 3a. V transpose (half) for tensor-core PV
    vtrans_kernel<<<dim3(NH * BATCH, S_LEN / 32, HD / 32), dim3(32, 8)>>>(qkv, vt);
    // 3b. attention -> a (half, merged heads, token layout)
    attn_mma_kernel<<<dim3(BATCH * NH, S_LEN / 64), 128, ATTN_SMEM_BYTES>>>(
        qkv, vt, a);
    // 4. x2 = x + a @ w_proj + b_proj         fp32 out
    gemm_f16<1><<<dim3(EMB / 128, NTOK / 128), 256, GEMM_SMEM_BYTES>>>(
        NTOK, EMB, EMB, a, wt_proj, b_proj, x, x2);
    // 5. ln2 (half output)
    ln_kernel<<<NTOK, 256>>>(x2, ln2_g, ln2_b, h);
    // 6. m = gelu(h @ w_fc + b_fc)            [4096, 4096] half out
    gemm_f16<2><<<dim3(4 * EMB / 128, NTOK / 128), 256, GEMM_SMEM_BYTES>>>(
        NTOK, 4 * EMB, EMB, h, wt_fc, b_fc, nullptr, mm);
    // 7. out = x2 + m @ w_out + b_out         fp32 out
    gemm_f16<1><<<dim3(EMB / 128, NTOK / 128), 256, GEMM_SMEM_BYTES>>>(
        NTOK, EMB, 4 * EMB, mm, wt_out, b_out, x2, out);
}

// round 17
// speedup vs baseline: 2.0780x; 1.0373x over previous
#include <cuda_runtime.h>
#include <cuda_fp16.h>
#include <math.h>
#include <stdint.h>

// ---------------------------------------------------------------------------
// Problem constants
// ---------------------------------------------------------------------------
#define S_LEN 1024
#define BATCH 4
#define EMB   1024
#define NH    16
#define HD    64
#define NTOK  (S_LEN * BATCH)
#define LN_EPS 1e-5f

// ---------------------------------------------------------------------------
// Scratch (device globals -- allocation-free kernel_launch requirement)
// ---------------------------------------------------------------------------
__device__ __half g_h  [NTOK * EMB];          // ln output (half)
__device__ __half g_qkv[NTOK * 3 * EMB];      // qkv (half)
__device__ __half g_a  [NTOK * EMB];          // attn out (half)
__device__ float  g_x2 [NTOK * EMB];          // x + attn residual (fp32)
__device__ __half g_m  [NTOK * 4 * EMB];      // gelu out (half)
__device__ __half g_wt [12 * EMB * EMB];      // half weights, NATURAL [K][N]

// ---------------------------------------------------------------------------
// helpers
// ---------------------------------------------------------------------------
// fp16 mma: m16n8k16, fp32 accumulate
__device__ __forceinline__ void mma_f16(
    float c[4], const uint32_t a[4], const uint32_t b[2])
{
    asm volatile(
        "mma.sync.aligned.m16n8k16.row.col.f32.f16.f16.f32 "
        "{%0,%1,%2,%3}, {%4,%5,%6,%7}, {%8,%9}, {%0,%1,%2,%3};\n"
        : "+f"(c[0]), "+f"(c[1]), "+f"(c[2]), "+f"(c[3])
        : "r"(a[0]), "r"(a[1]), "r"(a[2]), "r"(a[3]),
          "r"(b[0]), "r"(b[1]));
}

// ldmatrix x4 (b16)
#define LDSM_X4(r0, r1, r2, r3, addr)                                          \
    asm volatile(                                                              \
        "ldmatrix.sync.aligned.m8n8.x4.shared.b16 {%0,%1,%2,%3}, [%4];"        \
        : "=r"(r0), "=r"(r1), "=r"(r2), "=r"(r3) : "r"(addr))

// ldmatrix x4 transposed (b16): loads [k][n]-stored tiles as col-major frags
#define LDSM_X4_T(r0, r1, r2, r3, addr)                                        \
    asm volatile(                                                              \
        "ldmatrix.sync.aligned.m8n8.x4.trans.shared.b16 {%0,%1,%2,%3}, [%4];"  \
        : "=r"(r0), "=r"(r1), "=r"(r2), "=r"(r3) : "r"(addr))

// cp.async helpers
__device__ __forceinline__ void cp_async16(void* smem_ptr, const void* gptr) {
    uint32_t s = (uint32_t)__cvta_generic_to_shared(smem_ptr);
    asm volatile("cp.async.cg.shared.global [%0], [%1], 16;\n"
                 :: "r"(s), "l"(gptr));
}
__device__ __forceinline__ void cp_commit() {
    asm volatile("cp.async.commit_group;\n");
}
template <int N>
__device__ __forceinline__ void cp_wait() {
    asm volatile("cp.async.wait_group %0;\n" :: "n"(N));
}

// ---------------------------------------------------------------------------
// Weight convert (NO transpose): fp32 -> half, 8 elems/thread, coalesced.
// ---------------------------------------------------------------------------
__global__ void __launch_bounds__(256) wconv_kernel(
    const float* __restrict__ src, __half* __restrict__ dst, int n8)
{
    int i = blockIdx.x * 256 + threadIdx.x;
    if (i < n8) {
        const float4* s4 = reinterpret_cast<const float4*>(src) + 2 * (size_t)i;
        float4 a = s4[0], b = s4[1];
        __half2 h0 = __floats2half2_rn(a.x, a.y);
        __half2 h1 = __floats2half2_rn(a.z, a.w);
        __half2 h2 = __floats2half2_rn(b.x, b.y);
        __half2 h3 = __floats2half2_rn(b.z, b.w);
        uint4 o;
        o.x = *reinterpret_cast<uint32_t*>(&h0);
        o.y = *reinterpret_cast<uint32_t*>(&h1);
        o.z = *reinterpret_cast<uint32_t*>(&h2);
        o.w = *reinterpret_cast<uint32_t*>(&h3);
        reinterpret_cast<uint4*>(dst)[i] = o;
    }
}

// ---------------------------------------------------------------------------
// LayerNorm (writes half: only ever feeds GEMM A-operands)       (proven)
// ---------------------------------------------------------------------------
__global__ void __launch_bounds__(256) ln_kernel(
    const float* __restrict__ x, const float* __restrict__ gamma,
    const float* __restrict__ beta, __half* __restrict__ out)
{
    const int row = blockIdx.x;
    const int t   = threadIdx.x;
    const float4* xr = reinterpret_cast<const float4*>(x + (size_t)row * EMB);
    float4 v = xr[t];

    float s  = v.x + v.y + v.z + v.w;
    float sq = v.x * v.x + v.y * v.y + v.z * v.z + v.w * v.w;
    #pragma unroll
    for (int m = 16; m > 0; m >>= 1) {
        s  += __shfl_xor_sync(0xffffffffu, s,  m);
        sq += __shfl_xor_sync(0xffffffffu, sq, m);
    }

    __shared__ float sh_s[8], sh_q[8];
    __shared__ float sh_mean, sh_rstd;
    const int warp = t >> 5, lane = t & 31;
    if (lane == 0) { sh_s[warp] = s; sh_q[warp] = sq; }
    __syncthreads();
    if (t == 0) {
        float ts = 0.f, tq = 0.f;
        #pragma unroll
        for (int i = 0; i < 8; i++) { ts += sh_s[i]; tq += sh_q[i]; }
        float mean = ts * (1.0f / EMB);
        float var  = tq * (1.0f / EMB) - mean * mean;
        sh_mean = mean;
        sh_rstd = rsqrtf(var + LN_EPS);
    }
    __syncthreads();
    const float mean = sh_mean, rstd = sh_rstd;

    float4 g4 = reinterpret_cast<const float4*>(gamma)[t];
    float4 b4 = reinterpret_cast<const float4*>(beta)[t];
    __half2 h01 = __floats2half2_rn((v.x - mean) * rstd * g4.x + b4.x,
                                    (v.y - mean) * rstd * g4.y + b4.y);
    __half2 h23 = __floats2half2_rn((v.z - mean) * rstd * g4.z + b4.z,
                                    (v.w - mean) * rstd * g4.w + b4.w);
    __half2* o = reinterpret_cast<__half2*>(out + (size_t)row * EMB + t * 4);
    o[0] = h01; o[1] = h23;
}

// ---------------------------------------------------------------------------
// GELU (GPT-2 tanh approximation)
// ---------------------------------------------------------------------------
__device__ __forceinline__ float gelu_f(float x) {
    const float c = 0.7978845608028654f;
    float x3 = x * x * x;
    return 0.5f * x * (1.0f + tanhf(c * (x + 0.044715f * x3)));
}

// ---------------------------------------------------------------------------
// FP16 tensor-core GEMM, cp.async 3-stage pipeline, LDMATRIX fragment loads.
//   C[M,N] = A[M,K] @ W[K,N] + bias       (W in NATURAL [K][N] half layout)
//   EPI 0: bias -> HALF out   1: bias+res -> fp32 out   2: gelu -> half out
// A fragments: ldmatrix from [M-rows][k32] tiles (R13, proven).
// B fragments: ldmatrix.TRANS from [k32-rows][128 n] tiles; row pad 136
// halves (272B) -> trans-phase banks 4k mod 32, all distinct.
// ---------------------------------------------------------------------------
#define HST 20                            // A row stride in u32 (40 halves)
#define A_STG_U32 (128 * HST)             // 2560 u32
#define BST 68                            // B row stride in u32 (136 halves)
#define B_STG_U32 (32 * BST)              // 2176 u32
#define HG_STG (A_STG_U32 + B_STG_U32)    // 4736 u32 = 18944 B per stage
#define HNSTAGE 3
#define GEMM_SMEM_BYTES (HNSTAGE * HG_STG * 4)   // 56832 B

template <int EPI>
__global__ void __launch_bounds__(256, 2) gemm_f16(
    int M, int N, int K,
    const __half* __restrict__ A, const __half* __restrict__ W,
    const float* __restrict__ bias, const float* __restrict__ res,
    void* __restrict__ Cv)
{
    extern __shared__ uint32_t smem_u[];

    const int bm = blockIdx.y, bn = blockIdx.x;
    const int t    = threadIdx.x;
    const int warp = t >> 5, lane = t & 31;
    const int wm = warp >> 2;               // 0..1 : 64-row slab
    const int wn = warp & 3;                // 0..3 : 32-col slab
    const int g  = lane >> 2;               // 0..7
    const int q  = lane & 3;                // 0..3

    // A staging: 128 rows x 32 halves = 512 x 16B chunks; 2/thread
    const int arow = t >> 2;                // 0..63, +64
    const int acs  = t & 3;
    const __half* aSrc = A + (size_t)(bm * 128 + arow) * K + acs * 8;
    const int aDst = arow * HST + acs * 4;
    // B staging: 32 k-rows x 128 n-halves = 512 x 16B chunks; 2/thread
    const int brow = t >> 4;                // 0..15, +16
    const int bcs  = t & 15;
    const __half* bSrc = W + (size_t)brow * N + bn * 128 + bcs * 8;
    const int bDst = brow * BST + bcs * 4;

    const uint32_t sbase = (uint32_t)__cvta_generic_to_shared(smem_u);
    // A fragment offsets (non-trans, proven)
    const uint32_t aoff =
        ((((lane & 7) + ((lane & 8) ? 8 : 0)) * HST) + ((lane & 16) ? 4 : 0)) * 4;
    // B fragment offsets (TRANS): lanes 0-15 -> k-rows, lanes 16-31 -> +8 n
    const uint32_t boff =
        (lane & 15) * (BST * 4) + ((lane & 16) ? 16 : 0);

    float acc[4][4][4];
    #pragma unroll
    for (int mi = 0; mi < 4; mi++)
        #pragma unroll
        for (int ni = 0; ni < 4; ni++)
            #pragma unroll
            for (int j = 0; j < 4; j++) acc[mi][ni][j] = 0.f;

    #define ISSUE(stg, kt)                                                     \
        {                                                                      \
            uint32_t* as = smem_u + (stg) * HG_STG;                            \
            uint32_t* bs = as + A_STG_U32;                                     \
            _Pragma("unroll")                                                  \
            for (int i = 0; i < 2; i++) {                                      \
                cp_async16(as + aDst + i * (64 * HST),                         \
                           aSrc + (size_t)(kt) * 32 + (size_t)i * 64 * K);     \
                cp_async16(bs + bDst + i * (16 * BST),                         \
                           bSrc + ((size_t)(kt) * 32 + i * 16) * N);           \
            }                                                                  \
        }

    const int ntiles = K / 32;
    ISSUE(0, 0); cp_commit();
    ISSUE(1, 1); cp_commit();

    int buf = 0;
    for (int kt = 0; kt < ntiles; kt++) {
        cp_wait<1>();
        __syncthreads();

        if (kt + 2 < ntiles) {
            int nstg = buf + 2; if (nstg >= HNSTAGE) nstg -= HNSTAGE;
            ISSUE(nstg, kt + 2);
        }
        cp_commit();

        {
            const uint32_t abase =
                sbase + (buf * HG_STG + (wm * 64) * HST) * 4 + aoff;
            const uint32_t bbase =
                sbase + (buf * HG_STG + A_STG_U32) * 4 + (wn * 32) * 2 + boff;
            #pragma unroll
            for (int ks = 0; ks < 2; ks++) {
                uint32_t af[4][4], bf[4][2];
                #pragma unroll
                for (int mi = 0; mi < 4; mi++)
                    LDSM_X4(af[mi][0], af[mi][1], af[mi][2], af[mi][3],
                            abase + (mi * 16 * HST + ks * 8) * 4);
                #pragma unroll
                for (int nip = 0; nip < 2; nip++)
                    LDSM_X4_T(bf[2 * nip][0], bf[2 * nip][1],
                              bf[2 * nip + 1][0], bf[2 * nip + 1][1],
                              bbase + ks * 16 * (BST * 4) + nip * 32);
                #pragma unroll
                for (int mi = 0; mi < 4; mi++)
                    #pragma unroll
                    for (int ni = 0; ni < 4; ni++)
                        mma_f16(acc[mi][ni], af[mi], bf[ni]);
            }
        }

        buf++; if (buf == HNSTAGE) buf = 0;
    }
    #undef ISSUE

    // ---- epilogue ----
    float*  Cf = reinterpret_cast<float*>(Cv);
    __half* Ch = reinterpret_cast<__half*>(Cv);
    const int row_base = bm * 128 + wm * 64;
    const int col_base = bn * 128 + wn * 32;
    #pragma unroll
    for (int mi = 0; mi < 4; mi++) {
        #pragma unroll
        for (int ni = 0; ni < 4; ni++) {
            const int col = col_base + ni * 8 + 2 * q;
            const float b0 = bias[col], b1 = bias[col + 1];
            #pragma unroll
            for (int half_i = 0; half_i < 2; half_i++) {
                const int row = row_base + mi * 16 + g + half_i * 8;
                const size_t base = (size_t)row * N + col;
                float v0 = acc[mi][ni][half_i * 2 + 0] + b0;
                float v1 = acc[mi][ni][half_i * 2 + 1] + b1;
                if (EPI == 1) {
                    v0 += res[base]; v1 += res[base + 1];
                    *reinterpret_cast<float2*>(Cf + base) = make_float2(v0, v1);
                } else if (EPI == 2) {
                    *reinterpret_cast<__half2*>(Ch + base) =
                        __floats2half2_rn(gelu_f(v0), gelu_f(v1));
                } else {
                    *reinterpret_cast<__half2*>(Ch + base) =
                        __floats2half2_rn(v0, v1);
                }
            }
        }
    }
}

// ---------------------------------------------------------------------------
// Flash attention, fp16 mma m16n8k16 + ldmatrix, online softmax (fp32).
// Block = (b,h) x 64-row q tile; 4 warps, each owns 16 q rows.
// Q/K/V/P tiles in smem as half [64][72] (144B rows).
// K scores: non-trans fragments (tile rows = kv = n).           (R15 proven)
// V for PV: ldmatrix.TRANS straight from [kv][d] tile -- no pre-transpose.
// ---------------------------------------------------------------------------
#define ATSH 72                            // halves per row
#define ATRB (ATSH * 2)                    // row stride bytes (144)
#define ATTN_SMEM_BYTES (4 * 64 * ATSH * 2)   // Qs,Ks,Vs,Ps = 36864 B

__global__ void __launch_bounds__(128) attn_mma_kernel(
    const __half* __restrict__ qkv, __half* __restrict__ out)
{
    extern __shared__ __half smh[];
    __half* Qs = smh;                  // [64][ATSH]
    __half* Ks = smh + 64 * ATSH;
    __half* Vs = smh + 2 * 64 * ATSH;  // [kv][d]
    __half* Ps = smh + 3 * 64 * ATSH;

    const int bh = blockIdx.x, b = bh >> 4, h = bh & 15;
    const int q0 = blockIdx.y * 64;
    const int t = threadIdx.x, w = t >> 5, lane = t & 31;
    const int g = lane >> 2, q = lane & 3;
    const int wrow = w * 16;

    // fragment lane offsets (bytes)
    const uint32_t aoff =
        (((lane & 7) + ((lane & 8) ? 8 : 0)) * ATRB) + ((lane & 16) ? 16 : 0);
    const uint32_t boff =
        ((lane & 7) * ATRB) + ((lane & 8) ? 16 : 0) +
        ((lane & 16) ? 8 * ATRB : 0);
    const uint32_t vtoff =                         // TRANS: k-rows then +8 n
        (lane & 15) * ATRB + ((lane & 16) ? 16 : 0);

    const uint32_t qsm = (uint32_t)__cvta_generic_to_shared(Qs);
    const uint32_t ksm = (uint32_t)__cvta_generic_to_shared(Ks);
    const uint32_t vsm = (uint32_t)__cvta_generic_to_shared(Vs);
    const uint32_t psm = (uint32_t)__cvta_generic_to_shared(Ps);

    // ---- stage Q tile (64 x 64 half), 4 x 16B per thread ----
    #pragma unroll
    for (int i = 0; i < 4; i++) {
        int idx = t + i * 128;
        int r = idx >> 3, c = idx & 7;
        uint4 v = *reinterpret_cast<const uint4*>(
            qkv + ((size_t)(q0 + r) * BATCH + b) * (3 * EMB) + h * HD + c * 8);
        *reinterpret_cast<uint4*>(Qs + r * ATSH + c * 8) = v;
    }
    __syncthreads();

    // ---- Q fragments in registers for the whole KV loop ----
    uint32_t qf[4][4];
    {
        const uint32_t qbase = qsm + wrow * ATRB + aoff;
        #pragma unroll
        for (int ks = 0; ks < 4; ks++)
            LDSM_X4(qf[ks][0], qf[ks][1], qf[ks][2], qf[ks][3],
                    qbase + ks * 32);
    }
    __syncthreads();

    float o[8][4];
    #pragma unroll
    for (int nt = 0; nt < 8; nt++)
        #pragma unroll
        for (int j = 0; j < 4; j++) o[nt][j] = 0.f;
    float m0 = -1e30f, m1 = -1e30f, l0 = 0.f, l1 = 0.f;

    for (int kv0 = 0; kv0 < S_LEN; kv0 += 64) {
        // ---- stage K and V tiles, both [kv][d] ----
        #pragma unroll
        for (int i = 0; i < 4; i++) {
            int idx = t + i * 128;
            int r = idx >> 3, c = idx & 7;
            const size_t base =
                ((size_t)(kv0 + r) * BATCH + b) * (3 * EMB) + h * HD + c * 8;
            uint4 kvv = *reinterpret_cast<const uint4*>(qkv + base + EMB);
            *reinterpret_cast<uint4*>(Ks + r * ATSH + c * 8) = kvv;
            uint4 vv  = *reinterpret_cast<const uint4*>(qkv + base + 2 * EMB);
            *reinterpret_cast<uint4*>(Vs + r * ATSH + c * 8) = vv;
        }
        __syncthreads();

        // ---- scores: S[16][64] = Q[16][64] @ K[64][64]^T ----
        float sc[8][4];
        #pragma unroll
        for (int nt = 0; nt < 8; nt++)
            #pragma unroll
            for (int j = 0; j < 4; j++) sc[nt][j] = 0.f;

        #pragma unroll
        for (int ks = 0; ks < 4; ks++) {
            uint32_t bf[8][2];
            #pragma unroll
            for (int nip = 0; nip < 4; nip++)
                LDSM_X4(bf[2 * nip][0], bf[2 * nip][1],
                        bf[2 * nip + 1][0], bf[2 * nip + 1][1],
                        ksm + boff + nip * 16 * ATRB + ks * 32);
            #pragma unroll
            for (int nt = 0; nt < 8; nt++)
                mma_f16(sc[nt], qf[ks], bf[nt]);
        }

        // ---- online softmax (rows g and g+8; quad shfl over 64 cols) ----
        float mx0 = -1e30f, mx1 = -1e30f;
        #pragma unroll
        for (int nt = 0; nt < 8; nt++) {
            sc[nt][0] *= 0.125f; sc[nt][1] *= 0.125f;
            sc[nt][2] *= 0.125f; sc[nt][3] *= 0.125f;
            mx0 = fmaxf(mx0, fmaxf(sc[nt][0], sc[nt][1]));
            mx1 = fmaxf(mx1, fmaxf(sc[nt][2], sc[nt][3]));
        }
        mx0 = fmaxf(mx0, __shfl_xor_sync(0xffffffffu, mx0, 1));
        mx0 = fmaxf(mx0, __shfl_xor_sync(0xffffffffu, mx0, 2));
        mx1 = fmaxf(mx1, __shfl_xor_sync(0xffffffffu, mx1, 1));
        mx1 = fmaxf(mx1, __shfl_xor_sync(0xffffffffu, mx1, 2));

        const float mn0 = fmaxf(m0, mx0), mn1 = fmaxf(m1, mx1);
        const float a0 = __expf(m0 - mn0), a1 = __expf(m1 - mn1);
        float s0 = 0.f, s1 = 0.f;
        #pragma unroll
        for (int nt = 0; nt < 8; nt++) {
            float p0 = __expf(sc[nt][0] - mn0);
            float p1 = __expf(sc[nt][1] - mn0);
            float p2 = __expf(sc[nt][2] - mn1);
            float p3 = __expf(sc[nt][3] - mn1);
            s0 += p0 + p1; s1 += p2 + p3;
            *reinterpret_cast<__half2*>(
                Ps + (wrow + g) * ATSH + nt * 8 + 2 * q) =
                __floats2half2_rn(p0, p1);
            *reinterpret_cast<__half2*>(
                Ps + (wrow + g + 8) * ATSH + nt * 8 + 2 * q) =
                __floats2half2_rn(p2, p3);
        }
        s0 += __shfl_xor_sync(0xffffffffu, s0, 1);
        s0 += __shfl_xor_sync(0xffffffffu, s0, 2);
        s1 += __shfl_xor_sync(0xffffffffu, s1, 1);
        s1 += __shfl_xor_sync(0xffffffffu, s1, 2);

        l0 = l0 * a0 + s0; l1 = l1 * a1 + s1;
        m0 = mn0; m1 = mn1;
        #pragma unroll
        for (int nt = 0; nt < 8; nt++) {
            o[nt][0] *= a0; o[nt][1] *= a0;
            o[nt][2] *= a1; o[nt][3] *= a1;
        }
        __syncwarp();   // Ps produced+consumed within this warp

        // ---- PV: O[16][64] += P[16][64] @ V[64][64] (trans frags) ----
        #pragma unroll
        for (int ks = 0; ks < 4; ks++) {
            uint32_t af[4];
            LDSM_X4(af[0], af[1], af[2], af[3],
                    psm + wrow * ATRB + aoff + ks * 32);
            uint32_t bf[8][2];
            #pragma unroll
            for (int nip = 0; nip < 4; nip++)
                LDSM_X4_T(bf[2 * nip][0], bf[2 * nip][1],
                          bf[2 * nip + 1][0], bf[2 * nip + 1][1],
                          vsm + vtoff + ks * 16 * ATRB + nip * 32);
            #pragma unroll
            for (int nt = 0; nt < 8; nt++)
                mma_f16(o[nt], af, bf[nt]);
        }
        __syncthreads();   // protect Ks/Vs before next iteration
    }

    // ---- finalize: divide by l, store half ----
    const float inv0 = 1.0f / l0, inv1 = 1.0f / l1;
    const int s_row0 = q0 + wrow + g;
    #pragma unroll
    for (int nt = 0; nt < 8; nt++) {
        const int col = h * HD + nt * 8 + 2 * q;
        *reinterpret_cast<__half2*>(
            out + ((size_t)s_row0 * BATCH + b) * EMB + col) =
            __floats2half2_rn(o[nt][0] * inv0, o[nt][1] * inv0);
        *reinterpret_cast<__half2*>(
            out + ((size_t)(s_row0 + 8) * BATCH + b) * EMB + col) =
            __floats2half2_rn(o[nt][2] * inv1, o[nt][3] * inv1);
    }
}

// ---------------------------------------------------------------------------
// Launch
// ---------------------------------------------------------------------------
extern "C" void kernel_launch(void* const* d_in, const int* in_sizes, int n_in,
                              void* d_out, int out_size)
{
    const float* x      = (const float*)d_in[0];
    const float* ln1_g  = (const float*)d_in[1];
    const float* ln1_b  = (const float*)d_in[2];
    const float* w_attn = (const float*)d_in[3];
    const float* b_attn = (const float*)d_in[4];
    const float* w_proj = (const float*)d_in[5];
    const float* b_proj = (const float*)d_in[6];
    const float* ln2_g  = (const float*)d_in[7];
    const float* ln2_b  = (const float*)d_in[8];
    const float* w_fc   = (const float*)d_in[9];
    const float* b_fc   = (const float*)d_in[10];
    const float* w_out  = (const float*)d_in[11];
    const float* b_out  = (const float*)d_in[12];
    float* out = (float*)d_out;

    void *p_h, *p_qkv, *p_a, *p_x2, *p_m, *p_wt;
    cudaGetSymbolAddress(&p_h,   g_h);
    cudaGetSymbolAddress(&p_qkv, g_qkv);
    cudaGetSymbolAddress(&p_a,   g_a);
    cudaGetSymbolAddress(&p_x2,  g_x2);
    cudaGetSymbolAddress(&p_m,   g_m);
    cudaGetSymbolAddress(&p_wt,  g_wt);
    __half* h   = (__half*)p_h;
    __half* qkv = (__half*)p_qkv;
    __half* a   = (__half*)p_a;
    float*  x2  = (float*)p_x2;
    __half* mm  = (__half*)p_m;
    __half* wt  = (__half*)p_wt;

    __half* wt_attn = wt;                       // [E][3E]
    __half* wt_proj = wt + 3 * EMB * EMB;       // [E][E]
    __half* wt_fc   = wt + 4 * EMB * EMB;       // [E][4E]
    __half* wt_out  = wt + 8 * EMB * EMB;       // [4E][E]

    cudaFuncSetAttribute(attn_mma_kernel,
                         cudaFuncAttributeMaxDynamicSharedMemorySize,
                         ATTN_SMEM_BYTES);
    cudaFuncSetAttribute(gemm_f16<0>,
                         cudaFuncAttributeMaxDynamicSharedMemorySize,
                         GEMM_SMEM_BYTES);
    cudaFuncSetAttribute(gemm_f16<1>,
                         cudaFuncAttributeMaxDynamicSharedMemorySize,
                         GEMM_SMEM_BYTES);
    cudaFuncSetAttribute(gemm_f16<2>,
                         cudaFuncAttributeMaxDynamicSharedMemorySize,
                         GEMM_SMEM_BYTES);

    // 0. convert weights to half, keeping natural [K][N] layout
    wconv_kernel<<<(3 * EMB * EMB / 8 + 255) / 256, 256>>>(
        w_attn, wt_attn, 3 * EMB * EMB / 8);
    wconv_kernel<<<(EMB * EMB / 8 + 255) / 256, 256>>>(
        w_proj, wt_proj, EMB * EMB / 8);
    wconv_kernel<<<(4 * EMB * EMB / 8 + 255) / 256, 256>>>(
        w_fc, wt_fc, 4 * EMB * EMB / 8);
    wconv_kernel<<<(4 * EMB * EMB / 8 + 255) / 256, 256>>>(
        w_out, wt_out, 4 * EMB * EMB / 8);

    // 1. ln1 (half output)
    ln_kernel<<<NTOK, 256>>>(x, ln1_g, ln1_b, h);
    // 2. qkv = h @ w_attn + b_attn            [4096, 3072] HALF out
    gemm_f16<0><<<dim3(3 * EMB / 128, NTOK / 128), 256, GEMM_SMEM_BYTES>>>(
        NTOK, 3 * EMB, EMB, h, wt_attn, b_attn, nullptr, qkv);
    // 3. attention -> a (half, merged heads, token layout)
    attn_mma_kernel<<<dim3(BATCH * NH, S_LEN / 64), 128, ATTN_SMEM_BYTES>>>(
        qkv, a);
    // 4. x2 = x + a @ w_proj + b_proj         fp32 out
    gemm_f16<1><<<dim3(EMB / 128, NTOK / 128), 256, GEMM_SMEM_BYTES>>>(
        NTOK, EMB, EMB, a, wt_proj, b_proj, x, x2);
    // 5. ln2 (half output)
    ln_kernel<<<NTOK, 256>>>(x2, ln2_g, ln2_b, h);
    // 6. m = gelu(h @ w_fc + b_fc)            [4096, 4096] half out
    gemm_f16<2><<<dim3(4 * EMB / 128, NTOK / 128), 256, GEMM_SMEM_BYTES>>>(
        NTOK, 4 * EMB, EMB, h, wt_fc, b_fc, nullptr, mm);
    // 7. out = x2 + m @ w_out + b_out         fp32 out
    gemm_f16<1><<<dim3(EMB / 128, NTOK / 128), 256, GEMM_SMEM_BYTES>>>(
        NTOK, EMB, 4 * EMB, mm, wt_out, b_out, x2, out);
}